// round 1
// baseline (speedup 1.0000x reference)
#include <cuda_runtime.h>

#define NN 50000
#define EE 800000
#define E2T 850000   // EE + NN self loops
#define HH 4
#define CC 64
#define HC 256       // HH*CC

// Scratch (device globals; no allocation allowed)
__device__ float g_h[NN * HC];       // per-layer head features  [N,H,C]
__device__ float g_accum[NN * HC];   // unnormalized aggregation [N,H,C]
__device__ float g_feat[NN * CC];    // layer output after gelu  [N,C]
__device__ float g_es[NN * HH];
__device__ float g_ed[NN * HH];
__device__ float g_m[NN * HH];
__device__ float g_denom[NN * HH];

__device__ __forceinline__ float lrelu(float x) { return x >= 0.f ? x : 0.2f * x; }

// ---------------------------------------------------------------------------
// GEMM: h[N, 256] = X[N, IN] @ W[IN, 256].  16 nodes per 256-thread block.
// ---------------------------------------------------------------------------
template <int IN>
__global__ void gemm_kernel(const float* __restrict__ X, const float* __restrict__ W) {
    __shared__ float xs[16][IN];
    const int tid = threadIdx.x;
    const int base = blockIdx.x * 16;

    for (int i = tid; i < 16 * IN; i += 256) {
        int m = i / IN, k = i % IN;
        xs[m][k] = X[(base + m) * IN + k];
    }
    __syncthreads();

    float acc[16];
#pragma unroll
    for (int m = 0; m < 16; m++) acc[m] = 0.f;

    for (int k = 0; k < IN; k++) {
        float w = W[k * HC + tid];
#pragma unroll
        for (int m = 0; m < 16; m++) acc[m] += xs[m][k] * w;
    }
#pragma unroll
    for (int m = 0; m < 16; m++) g_h[(base + m) * HC + tid] = acc[m];
}

// ---------------------------------------------------------------------------
// Attention scores: es[n,h] = <h[n,h,:], a_src[h,:]>, ed likewise. Warp per (n,h).
// ---------------------------------------------------------------------------
__global__ void attn_kernel(const float* __restrict__ a_src, const float* __restrict__ a_dst) {
    int gt = blockIdx.x * blockDim.x + threadIdx.x;
    int w = gt >> 5, lane = gt & 31;
    if (w >= NN * HH) return;
    int n = w >> 2, h = w & 3;
    const float* hp = &g_h[n * HC + h * CC];
    float v0 = hp[lane], v1 = hp[lane + 32];
    float s = v0 * a_src[h * CC + lane] + v1 * a_src[h * CC + lane + 32];
    float d = v0 * a_dst[h * CC + lane] + v1 * a_dst[h * CC + lane + 32];
#pragma unroll
    for (int o = 16; o > 0; o >>= 1) {
        s += __shfl_xor_sync(0xffffffffu, s, o);
        d += __shfl_xor_sync(0xffffffffu, d, o);
    }
    if (lane == 0) { g_es[w] = s; g_ed[w] = d; }
}

// ---------------------------------------------------------------------------
// Init accumulators
// ---------------------------------------------------------------------------
__global__ void init_kernel() {
    int i = blockIdx.x * blockDim.x + threadIdx.x;
    if (i < NN * HC) g_accum[i] = 0.f;
    if (i < NN * HH) { g_m[i] = -1e30f; g_denom[i] = 0.f; }
}

// ---------------------------------------------------------------------------
// Pass 1 over edges: segment max of leaky_relu(es[src]+ed[dst]) per (dst,head)
// ---------------------------------------------------------------------------
__global__ void edge_max_kernel(const int* __restrict__ ei) {
    int i = blockIdx.x * blockDim.x + threadIdx.x;
    if (i >= E2T) return;
    int src, dst;
    if (i < EE) { src = ei[i]; dst = ei[EE + i]; }
    else        { src = i - EE; dst = src; }
#pragma unroll
    for (int h = 0; h < 4; h++) {
        float e = lrelu(g_es[src * 4 + h] + g_ed[dst * 4 + h]);
        float* addr = &g_m[dst * 4 + h];
        if (e >= 0.f) atomicMax((int*)addr, __float_as_int(e));
        else          atomicMin((unsigned int*)addr, __float_as_uint(e));
    }
}

// ---------------------------------------------------------------------------
// Pass 2 over edges: accumulate exp(e-m)*h[src] and exp(e-m) into dst.
// One warp per edge; vector red.global.add.v4.f32 (16B per reduction).
// ---------------------------------------------------------------------------
__global__ void edge_acc_kernel(const int* __restrict__ ei) {
    int gt = blockIdx.x * blockDim.x + threadIdx.x;
    int w = gt >> 5, lane = gt & 31;
    if (w >= E2T) return;
    int src, dst;
    if (w < EE) { src = ei[w]; dst = ei[EE + w]; }
    else        { src = w - EE; dst = src; }

    const float4* hp = (const float4*)&g_h[src * HC];
    float4* ap = (float4*)&g_accum[dst * HC];

#pragma unroll
    for (int p = 0; p < 2; p++) {
        int q = p * 32 + lane;            // float4 index within [0,64)
        int h = q >> 4;                   // 16 float4 chunks per head
        float e = lrelu(g_es[src * 4 + h] + g_ed[dst * 4 + h]);
        float ex = __expf(e - g_m[dst * 4 + h]);
        if ((q & 15) == 0) atomicAdd(&g_denom[dst * 4 + h], ex);
        float4 hv = hp[q];
        asm volatile("red.global.add.v4.f32 [%0], {%1,%2,%3,%4};"
                     :: "l"(ap + q),
                        "f"(hv.x * ex), "f"(hv.y * ex), "f"(hv.z * ex), "f"(hv.w * ex)
                     : "memory");
    }
}

// ---------------------------------------------------------------------------
// Finalize: normalize, head-mean, +bias, gelu(tanh approx, matching jax default)
// ---------------------------------------------------------------------------
__global__ void finalize_kernel(const float* __restrict__ bias) {
    int i = blockIdx.x * blockDim.x + threadIdx.x;
    if (i >= NN * CC) return;
    int n = i >> 6, c = i & 63;
    float s = 0.f;
#pragma unroll
    for (int h = 0; h < 4; h++)
        s += g_accum[n * HC + h * CC + c] / (g_denom[n * 4 + h] + 1e-16f);
    s = 0.25f * s + bias[c];
    float t = tanhf(0.7978845608028654f * (s + 0.044715f * s * s * s));
    g_feat[i] = 0.5f * s * (1.f + t);
}

// ---------------------------------------------------------------------------
// Final FC + sigmoid: out[n] = sigmoid(<feat[n,:], fc_W> + fc_b). Warp per node.
// ---------------------------------------------------------------------------
__global__ void fc_kernel(const float* __restrict__ fcW, const float* __restrict__ fcb,
                          float* __restrict__ out) {
    int gt = blockIdx.x * blockDim.x + threadIdx.x;
    int n = gt >> 5, lane = gt & 31;
    if (n >= NN) return;
    float s = g_feat[n * 64 + lane] * fcW[lane] + g_feat[n * 64 + lane + 32] * fcW[lane + 32];
#pragma unroll
    for (int o = 16; o > 0; o >>= 1) s += __shfl_xor_sync(0xffffffffu, s, o);
    if (lane == 0) out[n] = 1.f / (1.f + __expf(-(s + fcb[0])));
}

// ---------------------------------------------------------------------------

static void run_layer(const float* in, int in_dim, const float* W,
                      const float* a_src, const float* a_dst, const float* b,
                      const int* ei) {
    if (in_dim == 128) gemm_kernel<128><<<NN / 16, 256>>>(in, W);
    else               gemm_kernel<64><<<NN / 16, 256>>>(in, W);

    attn_kernel<<<(NN * HH * 32) / 256, 256>>>(a_src, a_dst);
    init_kernel<<<(NN * HC + 255) / 256, 256>>>();
    edge_max_kernel<<<(E2T + 255) / 256, 256>>>(ei);
    edge_acc_kernel<<<(E2T * 32 + 255) / 256, 256>>>(ei);
    finalize_kernel<<<(NN * CC + 255) / 256, 256>>>(b);
}

extern "C" void kernel_launch(void* const* d_in, const int* in_sizes, int n_in,
                              void* d_out, int out_size) {
    const float* x    = (const float*)d_in[0];
    const int*   ei   = (const int*)d_in[1];
    const float* W1   = (const float*)d_in[2];
    const float* as1  = (const float*)d_in[3];
    const float* ad1  = (const float*)d_in[4];
    const float* b1   = (const float*)d_in[5];
    const float* W2   = (const float*)d_in[6];
    const float* as2  = (const float*)d_in[7];
    const float* ad2  = (const float*)d_in[8];
    const float* b2   = (const float*)d_in[9];
    const float* W3   = (const float*)d_in[10];
    const float* as3  = (const float*)d_in[11];
    const float* ad3  = (const float*)d_in[12];
    const float* b3   = (const float*)d_in[13];
    const float* fcW  = (const float*)d_in[14];
    const float* fcb  = (const float*)d_in[15];

    float* feat_ptr = nullptr;
    cudaGetSymbolAddress((void**)&feat_ptr, g_feat);

    run_layer(x,        128, W1, as1, ad1, b1, ei);
    run_layer(feat_ptr,  64, W2, as2, ad2, b2, ei);
    run_layer(feat_ptr,  64, W3, as3, ad3, b3, ei);

    fc_kernel<<<(NN * 32 + 255) / 256, 256>>>(fcW, fcb, (float*)d_out);
}

// round 2
// speedup vs baseline: 1.4204x; 1.4204x over previous
#include <cuda_runtime.h>

#define NN 50000
#define EE 800000
#define E2T 850000   // EE + NN self loops
#define HH 4
#define CC 64
#define HC 256       // HH*CC

// Scratch (device globals; no allocation allowed)
__device__ float g_h[NN * HC];       // per-layer head features  [N, H*C]
__device__ float g_feat[NN * CC];    // layer output after gelu  [N, C]
__device__ float g_es[NN * HH];
__device__ float g_ed[NN * HH];
// CSR (built once; edge list identical across layers)
__device__ int g_cnt[NN];
__device__ int g_off[NN + 1];
__device__ int g_cur[NN];
__device__ int g_csr[E2T];           // src indices grouped by dst

__device__ __forceinline__ float lrelu(float x) { return x >= 0.f ? x : 0.2f * x; }

// ---------------------------------------------------------------------------
// CSR build
// ---------------------------------------------------------------------------
__global__ void hist_zero_kernel() {
    int i = blockIdx.x * blockDim.x + threadIdx.x;
    if (i < NN) g_cnt[i] = 0;
}

__global__ void hist_kernel(const int* __restrict__ ei) {
    int i = blockIdx.x * blockDim.x + threadIdx.x;
    if (i >= E2T) return;
    int dst = (i < EE) ? ei[EE + i] : (i - EE);
    atomicAdd(&g_cnt[dst], 1);
}

// single-block exclusive scan of g_cnt -> g_off (NN+1 entries)
__global__ void scan_kernel() {
    __shared__ int sdata[1024];
    int tid = threadIdx.x;
    int carry = 0;
    for (int base = 0; base < NN; base += 1024) {
        int i = base + tid;
        int v = (i < NN) ? g_cnt[i] : 0;
        sdata[tid] = v;
        __syncthreads();
        for (int off = 1; off < 1024; off <<= 1) {
            int t = (tid >= off) ? sdata[tid - off] : 0;
            __syncthreads();
            sdata[tid] += t;
            __syncthreads();
        }
        int incl = sdata[tid];
        if (i < NN) {
            g_off[i] = carry + incl - v;
            g_cur[i] = carry + incl - v;
        }
        int total = sdata[1023];
        __syncthreads();
        carry += total;
    }
    if (tid == 0) g_off[NN] = carry;
}

__global__ void scatter_kernel(const int* __restrict__ ei) {
    int i = blockIdx.x * blockDim.x + threadIdx.x;
    if (i >= E2T) return;
    int src, dst;
    if (i < EE) { src = ei[i]; dst = ei[EE + i]; }
    else        { src = i - EE; dst = src; }
    int pos = atomicAdd(&g_cur[dst], 1);
    g_csr[pos] = src;
}

// ---------------------------------------------------------------------------
// GEMM: h[N, 256] = X[N, IN] @ W[IN, 256].  16 nodes per 256-thread block.
// ---------------------------------------------------------------------------
template <int IN>
__global__ void gemm_kernel(const float* __restrict__ X, const float* __restrict__ W) {
    __shared__ float xs[16][IN];
    const int tid = threadIdx.x;
    const int base = blockIdx.x * 16;

    for (int i = tid; i < 16 * IN; i += 256) {
        int m = i / IN, k = i % IN;
        xs[m][k] = X[(base + m) * IN + k];
    }
    __syncthreads();

    float acc[16];
#pragma unroll
    for (int m = 0; m < 16; m++) acc[m] = 0.f;

    for (int k = 0; k < IN; k++) {
        float w = W[k * HC + tid];
#pragma unroll
        for (int m = 0; m < 16; m++) acc[m] += xs[m][k] * w;
    }
#pragma unroll
    for (int m = 0; m < 16; m++) g_h[(base + m) * HC + tid] = acc[m];
}

// ---------------------------------------------------------------------------
// Attention scores: es[n,h] = <h[n,h,:], a_src[h,:]>, ed likewise. Warp per (n,h).
// ---------------------------------------------------------------------------
__global__ void attn_kernel(const float* __restrict__ a_src, const float* __restrict__ a_dst) {
    int gt = blockIdx.x * blockDim.x + threadIdx.x;
    int w = gt >> 5, lane = gt & 31;
    if (w >= NN * HH) return;
    int n = w >> 2, h = w & 3;
    const float* hp = &g_h[n * HC + h * CC];
    float v0 = hp[lane], v1 = hp[lane + 32];
    float s = v0 * a_src[h * CC + lane] + v1 * a_src[h * CC + lane + 32];
    float d = v0 * a_dst[h * CC + lane] + v1 * a_dst[h * CC + lane + 32];
#pragma unroll
    for (int o = 16; o > 0; o >>= 1) {
        s += __shfl_xor_sync(0xffffffffu, s, o);
        d += __shfl_xor_sync(0xffffffffu, d, o);
    }
    if (lane == 0) { g_es[w] = s; g_ed[w] = d; }
}

// ---------------------------------------------------------------------------
// Fused softmax-aggregate + normalize + head-mean + bias + gelu.
// One 64-thread block per dst node; thread c owns channel c for all 4 heads.
// ---------------------------------------------------------------------------
__global__ void __launch_bounds__(64) aggregate_kernel(const float* __restrict__ bias) {
    const int n = blockIdx.x;
    const int c = threadIdx.x;           // 0..63
    const int row0 = g_off[n], row1 = g_off[n + 1];

    const float4 edv = *(const float4*)&g_ed[n * 4];

    // --- Pass 1: per-head max over incoming edges (strided over threads) ---
    float m0 = -1e30f, m1 = -1e30f, m2 = -1e30f, m3 = -1e30f;
    for (int k = row0 + c; k < row1; k += 64) {
        int s = __ldg(&g_csr[k]);
        float4 esv = __ldg((const float4*)&g_es[s * 4]);
        m0 = fmaxf(m0, lrelu(esv.x + edv.x));
        m1 = fmaxf(m1, lrelu(esv.y + edv.y));
        m2 = fmaxf(m2, lrelu(esv.z + edv.z));
        m3 = fmaxf(m3, lrelu(esv.w + edv.w));
    }
#pragma unroll
    for (int o = 16; o > 0; o >>= 1) {
        m0 = fmaxf(m0, __shfl_xor_sync(0xffffffffu, m0, o));
        m1 = fmaxf(m1, __shfl_xor_sync(0xffffffffu, m1, o));
        m2 = fmaxf(m2, __shfl_xor_sync(0xffffffffu, m2, o));
        m3 = fmaxf(m3, __shfl_xor_sync(0xffffffffu, m3, o));
    }
    __shared__ float sm[2][4];
    if ((c & 31) == 0) {
        sm[c >> 5][0] = m0; sm[c >> 5][1] = m1;
        sm[c >> 5][2] = m2; sm[c >> 5][3] = m3;
    }
    __syncthreads();
    m0 = fmaxf(sm[0][0], sm[1][0]);
    m1 = fmaxf(sm[0][1], sm[1][1]);
    m2 = fmaxf(sm[0][2], sm[1][2]);
    m3 = fmaxf(sm[0][3], sm[1][3]);

    // --- Pass 2: accumulate exp-weighted h[src] and denominators in regs ---
    float a0 = 0.f, a1 = 0.f, a2 = 0.f, a3 = 0.f;
    float d0 = 0.f, d1 = 0.f, d2 = 0.f, d3 = 0.f;
    for (int k = row0; k < row1; k++) {
        int s = __ldg(&g_csr[k]);
        float4 esv = __ldg((const float4*)&g_es[s * 4]);
        float w0 = __expf(lrelu(esv.x + edv.x) - m0);
        float w1 = __expf(lrelu(esv.y + edv.y) - m1);
        float w2 = __expf(lrelu(esv.z + edv.z) - m2);
        float w3 = __expf(lrelu(esv.w + edv.w) - m3);
        const float* hp = &g_h[s * HC];
        a0 += w0 * __ldg(&hp[c]);
        a1 += w1 * __ldg(&hp[64 + c]);
        a2 += w2 * __ldg(&hp[128 + c]);
        a3 += w3 * __ldg(&hp[192 + c]);
        d0 += w0; d1 += w1; d2 += w2; d3 += w3;
    }

    float s = 0.25f * (a0 / (d0 + 1e-16f) + a1 / (d1 + 1e-16f) +
                       a2 / (d2 + 1e-16f) + a3 / (d3 + 1e-16f)) + bias[c];
    float t = tanhf(0.7978845608028654f * (s + 0.044715f * s * s * s));
    g_feat[n * CC + c] = 0.5f * s * (1.f + t);
}

// ---------------------------------------------------------------------------
// Final FC + sigmoid: out[n] = sigmoid(<feat[n,:], fc_W> + fc_b). Warp per node.
// ---------------------------------------------------------------------------
__global__ void fc_kernel(const float* __restrict__ fcW, const float* __restrict__ fcb,
                          float* __restrict__ out) {
    int gt = blockIdx.x * blockDim.x + threadIdx.x;
    int n = gt >> 5, lane = gt & 31;
    if (n >= NN) return;
    float s = g_feat[n * 64 + lane] * fcW[lane] + g_feat[n * 64 + lane + 32] * fcW[lane + 32];
#pragma unroll
    for (int o = 16; o > 0; o >>= 1) s += __shfl_xor_sync(0xffffffffu, s, o);
    if (lane == 0) out[n] = 1.f / (1.f + __expf(-(s + fcb[0])));
}

// ---------------------------------------------------------------------------

static void run_layer(const float* in, int in_dim, const float* W,
                      const float* a_src, const float* a_dst, const float* b) {
    if (in_dim == 128) gemm_kernel<128><<<NN / 16, 256>>>(in, W);
    else               gemm_kernel<64><<<NN / 16, 256>>>(in, W);
    attn_kernel<<<(NN * HH * 32) / 256, 256>>>(a_src, a_dst);
    aggregate_kernel<<<NN, 64>>>(b);
}

extern "C" void kernel_launch(void* const* d_in, const int* in_sizes, int n_in,
                              void* d_out, int out_size) {
    const float* x    = (const float*)d_in[0];
    const int*   ei   = (const int*)d_in[1];
    const float* W1   = (const float*)d_in[2];
    const float* as1  = (const float*)d_in[3];
    const float* ad1  = (const float*)d_in[4];
    const float* b1   = (const float*)d_in[5];
    const float* W2   = (const float*)d_in[6];
    const float* as2  = (const float*)d_in[7];
    const float* ad2  = (const float*)d_in[8];
    const float* b2   = (const float*)d_in[9];
    const float* W3   = (const float*)d_in[10];
    const float* as3  = (const float*)d_in[11];
    const float* ad3  = (const float*)d_in[12];
    const float* b3   = (const float*)d_in[13];
    const float* fcW  = (const float*)d_in[14];
    const float* fcb  = (const float*)d_in[15];

    float* feat_ptr = nullptr;
    cudaGetSymbolAddress((void**)&feat_ptr, g_feat);

    // Build CSR once (edge list identical for all 3 layers)
    hist_zero_kernel<<<(NN + 255) / 256, 256>>>();
    hist_kernel<<<(E2T + 255) / 256, 256>>>(ei);
    scan_kernel<<<1, 1024>>>();
    scatter_kernel<<<(E2T + 255) / 256, 256>>>(ei);

    run_layer(x,        128, W1, as1, ad1, b1);
    run_layer(feat_ptr,  64, W2, as2, ad2, b2);
    run_layer(feat_ptr,  64, W3, as3, ad3, b3);

    fc_kernel<<<(NN * 32 + 255) / 256, 256>>>(fcW, fcb, (float*)d_out);
}

// round 3
// speedup vs baseline: 1.8811x; 1.3243x over previous
#include <cuda_runtime.h>

#define NN 50000
#define EE 800000
#define E2T 850000   // EE + NN self loops
#define HH 4
#define CC 64
#define HC 256       // HH*CC

// Scratch (device globals; no allocation allowed)
__device__ float g_h[NN * HC];       // per-layer head features  [N, H*C]
__device__ float g_feat[NN * CC];    // layer output after gelu  [N, C]
__device__ float g_es[NN * HH];
__device__ float g_ed[NN * HH];
// CSR (built once; edge list identical across layers)
__device__ int g_cnt[NN];
__device__ int g_off[NN + 1];
__device__ int g_cur[NN];
__device__ int g_csr[E2T];           // src indices grouped by dst

__device__ __forceinline__ float lrelu(float x) { return x >= 0.f ? x : 0.2f * x; }

// ---------------------------------------------------------------------------
// CSR build
// ---------------------------------------------------------------------------
__global__ void hist_zero_kernel() {
    int i = blockIdx.x * blockDim.x + threadIdx.x;
    if (i < NN) g_cnt[i] = 0;
}

__global__ void hist_kernel(const int* __restrict__ ei) {
    int i = blockIdx.x * blockDim.x + threadIdx.x;
    if (i >= E2T) return;
    int dst = (i < EE) ? ei[EE + i] : (i - EE);
    atomicAdd(&g_cnt[dst], 1);
}

// single-block exclusive scan of g_cnt -> g_off (shfl-based)
__global__ void scan_kernel() {
    __shared__ int wsum[32];
    __shared__ int s_total;
    const int tid = threadIdx.x;
    const int lane = tid & 31, wid = tid >> 5;
    int carry = 0;
    for (int base = 0; base < NN; base += 1024) {
        int i = base + tid;
        int v = (i < NN) ? g_cnt[i] : 0;
        // inclusive warp scan
        int s = v;
#pragma unroll
        for (int o = 1; o < 32; o <<= 1) {
            int t = __shfl_up_sync(0xffffffffu, s, o);
            if (lane >= o) s += t;
        }
        if (lane == 31) wsum[wid] = s;
        __syncthreads();
        if (wid == 0) {
            int w = wsum[lane];
#pragma unroll
            for (int o = 1; o < 32; o <<= 1) {
                int t = __shfl_up_sync(0xffffffffu, w, o);
                if (lane >= o) w += t;
            }
            wsum[lane] = w;
            if (lane == 31) s_total = w;
        }
        __syncthreads();
        int incl = s + (wid ? wsum[wid - 1] : 0);
        if (i < NN) {
            g_off[i] = carry + incl - v;
            g_cur[i] = carry + incl - v;
        }
        carry += s_total;
        __syncthreads();
    }
    if (tid == 0) g_off[NN] = carry;
}

__global__ void scatter_kernel(const int* __restrict__ ei) {
    int i = blockIdx.x * blockDim.x + threadIdx.x;
    if (i >= E2T) return;
    int src, dst;
    if (i < EE) { src = ei[i]; dst = ei[EE + i]; }
    else        { src = i - EE; dst = src; }
    int pos = atomicAdd(&g_cur[dst], 1);
    g_csr[pos] = src;
}

// ---------------------------------------------------------------------------
// GEMM: h[N, 256] = X[N, IN] @ W[IN, 256].
// 16 nodes x 256 cols per 64-thread block; thread owns 4 cols (4*tid..4*tid+3).
// X staged transposed in smem (padded) so inner loop is 4xLDS.128 + 1xLDG.128
// + 64 FFMA per k.
// ---------------------------------------------------------------------------
#define TM 16
template <int IN>
__global__ void __launch_bounds__(64) gemm_kernel(const float* __restrict__ X,
                                                  const float* __restrict__ W) {
    __shared__ float xs[IN][TM + 4];   // pad 4 keeps float4 alignment per row
    const int tid = threadIdx.x;
    const int base = blockIdx.x * TM;  // NN % TM == 0

    // Load X tile coalesced, store transposed
    const float4* X4 = (const float4*)X;
    for (int i4 = tid; i4 < TM * (IN / 4); i4 += 64) {
        int m = i4 / (IN / 4), kk = i4 % (IN / 4);
        float4 v = X4[(base + m) * (IN / 4) + kk];
        xs[4 * kk + 0][m] = v.x;
        xs[4 * kk + 1][m] = v.y;
        xs[4 * kk + 2][m] = v.z;
        xs[4 * kk + 3][m] = v.w;
    }
    __syncthreads();

    float4 acc[TM];
#pragma unroll
    for (int m = 0; m < TM; m++) acc[m] = make_float4(0.f, 0.f, 0.f, 0.f);

    const float4* W4 = (const float4*)W;
    for (int k = 0; k < IN; k++) {
        float4 w = W4[k * 64 + tid];
#pragma unroll
        for (int mm = 0; mm < TM / 4; mm++) {
            float4 xv = *(const float4*)&xs[k][4 * mm];
            acc[4*mm+0].x += xv.x * w.x; acc[4*mm+0].y += xv.x * w.y;
            acc[4*mm+0].z += xv.x * w.z; acc[4*mm+0].w += xv.x * w.w;
            acc[4*mm+1].x += xv.y * w.x; acc[4*mm+1].y += xv.y * w.y;
            acc[4*mm+1].z += xv.y * w.z; acc[4*mm+1].w += xv.y * w.w;
            acc[4*mm+2].x += xv.z * w.x; acc[4*mm+2].y += xv.z * w.y;
            acc[4*mm+2].z += xv.z * w.z; acc[4*mm+2].w += xv.z * w.w;
            acc[4*mm+3].x += xv.w * w.x; acc[4*mm+3].y += xv.w * w.y;
            acc[4*mm+3].z += xv.w * w.z; acc[4*mm+3].w += xv.w * w.w;
        }
    }

    float4* H4 = (float4*)g_h;
#pragma unroll
    for (int m = 0; m < TM; m++)
        H4[(base + m) * 64 + tid] = acc[m];
}

// ---------------------------------------------------------------------------
// Attention scores: es[n,h] = <h[n,h,:], a_src[h,:]>, ed likewise. Warp per (n,h).
// ---------------------------------------------------------------------------
__global__ void attn_kernel(const float* __restrict__ a_src, const float* __restrict__ a_dst) {
    int gt = blockIdx.x * blockDim.x + threadIdx.x;
    int w = gt >> 5, lane = gt & 31;
    if (w >= NN * HH) return;
    int n = w >> 2, h = w & 3;
    const float* hp = &g_h[n * HC + h * CC];
    float v0 = hp[lane], v1 = hp[lane + 32];
    float s = v0 * a_src[h * CC + lane] + v1 * a_src[h * CC + lane + 32];
    float d = v0 * a_dst[h * CC + lane] + v1 * a_dst[h * CC + lane + 32];
#pragma unroll
    for (int o = 16; o > 0; o >>= 1) {
        s += __shfl_xor_sync(0xffffffffu, s, o);
        d += __shfl_xor_sync(0xffffffffu, d, o);
    }
    if (lane == 0) { g_es[w] = s; g_ed[w] = d; }
}

// ---------------------------------------------------------------------------
// Fused softmax-aggregate + normalize + head-mean + bias + gelu.
// One 64-thread block per dst node. Thread t owns channels 4t..4t+3
// (all within head t>>4). Weights computed once per edge in smem chunks.
// ---------------------------------------------------------------------------
#define CHUNK 64
__global__ void __launch_bounds__(64) aggregate_kernel(const float* __restrict__ bias) {
    __shared__ int    ss[CHUNK];
    __shared__ float4 ws[CHUNK];
    __shared__ float  outsm[256];
    __shared__ float  smx[2][4];

    const int n = blockIdx.x;
    const int t = threadIdx.x;           // 0..63
    const int ht = t >> 4;               // head of channels 4t..4t+3
    const int row0 = g_off[n], row1 = g_off[n + 1];
    const float4 edv = *(const float4*)&g_ed[n * 4];
    const float bv = bias[t];

    // --- Pass 1: per-head max over incoming edges (strided over threads) ---
    float m0 = -1e30f, m1 = -1e30f, m2 = -1e30f, m3 = -1e30f;
    for (int k = row0 + t; k < row1; k += 64) {
        int s = __ldg(&g_csr[k]);
        float4 esv = __ldg((const float4*)&g_es[s * 4]);
        m0 = fmaxf(m0, lrelu(esv.x + edv.x));
        m1 = fmaxf(m1, lrelu(esv.y + edv.y));
        m2 = fmaxf(m2, lrelu(esv.z + edv.z));
        m3 = fmaxf(m3, lrelu(esv.w + edv.w));
    }
#pragma unroll
    for (int o = 16; o > 0; o >>= 1) {
        m0 = fmaxf(m0, __shfl_xor_sync(0xffffffffu, m0, o));
        m1 = fmaxf(m1, __shfl_xor_sync(0xffffffffu, m1, o));
        m2 = fmaxf(m2, __shfl_xor_sync(0xffffffffu, m2, o));
        m3 = fmaxf(m3, __shfl_xor_sync(0xffffffffu, m3, o));
    }
    if ((t & 31) == 0) {
        smx[t >> 5][0] = m0; smx[t >> 5][1] = m1;
        smx[t >> 5][2] = m2; smx[t >> 5][3] = m3;
    }
    __syncthreads();
    m0 = fmaxf(smx[0][0], smx[1][0]);
    m1 = fmaxf(smx[0][1], smx[1][1]);
    m2 = fmaxf(smx[0][2], smx[1][2]);
    m3 = fmaxf(smx[0][3], smx[1][3]);

    // --- Pass 2: chunked. Weights once per edge -> smem; then gather h. ---
    float a0 = 0.f, a1 = 0.f, a2 = 0.f, a3 = 0.f, dsum = 0.f;
    for (int base = row0; base < row1; base += CHUNK) {
        int cnt = min(CHUNK, row1 - base);
        if (t < cnt) {
            int s = __ldg(&g_csr[base + t]);
            ss[t] = s;
            float4 esv = __ldg((const float4*)&g_es[s * 4]);
            ws[t] = make_float4(__expf(lrelu(esv.x + edv.x) - m0),
                                __expf(lrelu(esv.y + edv.y) - m1),
                                __expf(lrelu(esv.z + edv.z) - m2),
                                __expf(lrelu(esv.w + edv.w) - m3));
        }
        __syncthreads();
#pragma unroll 2
        for (int e = 0; e < cnt; e++) {
            float wv = ((const float*)&ws[e])[ht];
            float4 hv = *(const float4*)&g_h[ss[e] * HC + 4 * t];
            a0 += wv * hv.x; a1 += wv * hv.y;
            a2 += wv * hv.z; a3 += wv * hv.w;
            dsum += wv;
        }
        __syncthreads();
    }

    float inv = 1.f / (dsum + 1e-16f);
    *(float4*)&outsm[4 * t] = make_float4(a0 * inv, a1 * inv, a2 * inv, a3 * inv);
    __syncthreads();

    // head mean + bias + gelu (thread t -> channel t)
    float s = 0.25f * (outsm[t] + outsm[64 + t] + outsm[128 + t] + outsm[192 + t]) + bv;
    float tt = tanhf(0.7978845608028654f * (s + 0.044715f * s * s * s));
    g_feat[n * CC + t] = 0.5f * s * (1.f + tt);
}

// ---------------------------------------------------------------------------
// Final FC + sigmoid: out[n] = sigmoid(<feat[n,:], fc_W> + fc_b). Warp per node.
// ---------------------------------------------------------------------------
__global__ void fc_kernel(const float* __restrict__ fcW, const float* __restrict__ fcb,
                          float* __restrict__ out) {
    int gt = blockIdx.x * blockDim.x + threadIdx.x;
    int n = gt >> 5, lane = gt & 31;
    if (n >= NN) return;
    float s = g_feat[n * 64 + lane] * fcW[lane] + g_feat[n * 64 + lane + 32] * fcW[lane + 32];
#pragma unroll
    for (int o = 16; o > 0; o >>= 1) s += __shfl_xor_sync(0xffffffffu, s, o);
    if (lane == 0) out[n] = 1.f / (1.f + __expf(-(s + fcb[0])));
}

// ---------------------------------------------------------------------------

static void run_layer(const float* in, int in_dim, const float* W,
                      const float* a_src, const float* a_dst, const float* b) {
    if (in_dim == 128) gemm_kernel<128><<<NN / TM, 64>>>(in, W);
    else               gemm_kernel<64><<<NN / TM, 64>>>(in, W);
    attn_kernel<<<(NN * HH * 32) / 256, 256>>>(a_src, a_dst);
    aggregate_kernel<<<NN, 64>>>(b);
}

extern "C" void kernel_launch(void* const* d_in, const int* in_sizes, int n_in,
                              void* d_out, int out_size) {
    const float* x    = (const float*)d_in[0];
    const int*   ei   = (const int*)d_in[1];
    const float* W1   = (const float*)d_in[2];
    const float* as1  = (const float*)d_in[3];
    const float* ad1  = (const float*)d_in[4];
    const float* b1   = (const float*)d_in[5];
    const float* W2   = (const float*)d_in[6];
    const float* as2  = (const float*)d_in[7];
    const float* ad2  = (const float*)d_in[8];
    const float* b2   = (const float*)d_in[9];
    const float* W3   = (const float*)d_in[10];
    const float* as3  = (const float*)d_in[11];
    const float* ad3  = (const float*)d_in[12];
    const float* b3   = (const float*)d_in[13];
    const float* fcW  = (const float*)d_in[14];
    const float* fcb  = (const float*)d_in[15];

    float* feat_ptr = nullptr;
    cudaGetSymbolAddress((void**)&feat_ptr, g_feat);

    // Build CSR once (edge list identical for all 3 layers)
    hist_zero_kernel<<<(NN + 255) / 256, 256>>>();
    hist_kernel<<<(E2T + 255) / 256, 256>>>(ei);
    scan_kernel<<<1, 1024>>>();
    scatter_kernel<<<(E2T + 255) / 256, 256>>>(ei);

    run_layer(x,        128, W1, as1, ad1, b1);
    run_layer(feat_ptr,  64, W2, as2, ad2, b2);
    run_layer(feat_ptr,  64, W3, as3, ad3, b3);

    fc_kernel<<<(NN * 32 + 255) / 256, 256>>>(fcW, fcb, (float*)d_out);
}

// round 6
// speedup vs baseline: 2.2006x; 1.1698x over previous
#include <cuda_runtime.h>
#include <cuda_fp16.h>

#define NN 50000
#define EE 800000
#define E2T 850000   // EE + NN self loops
#define HH 4
#define CC 64
#define HC 256       // HH*CC

// Scratch (device globals; no allocation allowed)
__device__ __half g_hh[NN * HC];     // fp16 head features for the edge gather
__device__ float  g_feat[NN * CC];   // layer output after gelu  [N, C]
__device__ float  g_es[NN * HH];
__device__ float  g_ed[NN * HH];
// CSR (built once; edge list identical across layers)
__device__ int g_cnt[NN];
__device__ int g_off[NN + 1];
__device__ int g_cur[NN];
__device__ int g_csr[E2T];           // src indices grouped by dst

__device__ __forceinline__ float lrelu(float x) { return x >= 0.f ? x : 0.2f * x; }

// ---------------------------------------------------------------------------
// CSR build
// ---------------------------------------------------------------------------
__global__ void hist_zero_kernel() {
    int i = blockIdx.x * blockDim.x + threadIdx.x;
    if (i < NN) g_cnt[i] = 0;
}

__global__ void hist_kernel(const int* __restrict__ ei) {
    int i = blockIdx.x * blockDim.x + threadIdx.x;
    if (i >= E2T) return;
    int dst = (i < EE) ? ei[EE + i] : (i - EE);
    atomicAdd(&g_cnt[dst], 1);
}

// single-block exclusive scan of g_cnt -> g_off (shfl-based)
__global__ void scan_kernel() {
    __shared__ int wsum[32];
    __shared__ int s_total;
    const int tid = threadIdx.x;
    const int lane = tid & 31, wid = tid >> 5;
    int carry = 0;
    for (int base = 0; base < NN; base += 1024) {
        int i = base + tid;
        int v = (i < NN) ? g_cnt[i] : 0;
        int s = v;
#pragma unroll
        for (int o = 1; o < 32; o <<= 1) {
            int t = __shfl_up_sync(0xffffffffu, s, o);
            if (lane >= o) s += t;
        }
        if (lane == 31) wsum[wid] = s;
        __syncthreads();
        if (wid == 0) {
            int w = wsum[lane];
#pragma unroll
            for (int o = 1; o < 32; o <<= 1) {
                int t = __shfl_up_sync(0xffffffffu, w, o);
                if (lane >= o) w += t;
            }
            wsum[lane] = w;
            if (lane == 31) s_total = w;
        }
        __syncthreads();
        int incl = s + (wid ? wsum[wid - 1] : 0);
        if (i < NN) {
            g_off[i] = carry + incl - v;
            g_cur[i] = carry + incl - v;
        }
        carry += s_total;
        __syncthreads();
    }
    if (tid == 0) g_off[NN] = carry;
}

__global__ void scatter_kernel(const int* __restrict__ ei) {
    int i = blockIdx.x * blockDim.x + threadIdx.x;
    if (i >= E2T) return;
    int src, dst;
    if (i < EE) { src = ei[i]; dst = ei[EE + i]; }
    else        { src = i - EE; dst = src; }
    int pos = atomicAdd(&g_cur[dst], 1);
    g_csr[pos] = src;
}

// ---------------------------------------------------------------------------
// Fused GEMM + attention scores.
// h[N,256] = X[N,IN] @ W[IN,256]; 16 nodes x 256 cols per 64-thread block,
// thread t owns cols 4t..4t+3 (head ht=t>>4, channels 4*(t&15)..+3).
// Epilogue: es/ed dot products reduced over the 16 threads of each head group;
// h written only as fp16 (for the edge gather). No fp32 h array at all.
// ---------------------------------------------------------------------------
#define TM 16
template <int IN>
__global__ void __launch_bounds__(64) gemm_kernel(const float* __restrict__ X,
                                                  const float* __restrict__ W,
                                                  const float* __restrict__ a_src,
                                                  const float* __restrict__ a_dst) {
    __shared__ float xs[IN][TM + 4];   // pad keeps float4 alignment per row
    const int tid = threadIdx.x;
    const int base = blockIdx.x * TM;  // NN % TM == 0

    // Load X tile coalesced, store transposed
    const float4* X4 = (const float4*)X;
    for (int i4 = tid; i4 < TM * (IN / 4); i4 += 64) {
        int m = i4 / (IN / 4), kk = i4 % (IN / 4);
        float4 v = X4[(base + m) * (IN / 4) + kk];
        xs[4 * kk + 0][m] = v.x;
        xs[4 * kk + 1][m] = v.y;
        xs[4 * kk + 2][m] = v.z;
        xs[4 * kk + 3][m] = v.w;
    }
    __syncthreads();

    float4 acc[TM];
#pragma unroll
    for (int m = 0; m < TM; m++) acc[m] = make_float4(0.f, 0.f, 0.f, 0.f);

    const float4* W4 = (const float4*)W;
    for (int k = 0; k < IN; k++) {
        float4 w = W4[k * 64 + tid];
#pragma unroll
        for (int mm = 0; mm < TM / 4; mm++) {
            float4 xv = *(const float4*)&xs[k][4 * mm];
            acc[4*mm+0].x += xv.x * w.x; acc[4*mm+0].y += xv.x * w.y;
            acc[4*mm+0].z += xv.x * w.z; acc[4*mm+0].w += xv.x * w.w;
            acc[4*mm+1].x += xv.y * w.x; acc[4*mm+1].y += xv.y * w.y;
            acc[4*mm+1].z += xv.y * w.z; acc[4*mm+1].w += xv.y * w.w;
            acc[4*mm+2].x += xv.z * w.x; acc[4*mm+2].y += xv.z * w.y;
            acc[4*mm+2].z += xv.z * w.z; acc[4*mm+2].w += xv.z * w.w;
            acc[4*mm+3].x += xv.w * w.x; acc[4*mm+3].y += xv.w * w.y;
            acc[4*mm+3].z += xv.w * w.z; acc[4*mm+3].w += xv.w * w.w;
        }
    }

    // attention vectors for my 4 channels (head ht, channels 4*(t&15)..+3)
    const int ht = tid >> 4;
    const float4 asv = *(const float4*)&a_src[ht * CC + 4 * (tid & 15)];
    const float4 adv = *(const float4*)&a_dst[ht * CC + 4 * (tid & 15)];

#pragma unroll
    for (int m = 0; m < TM; m++) {
        float4 r = acc[m];
        // fp16 copy for the edge gather
        __half2 h0 = __floats2half2_rn(r.x, r.y);
        __half2 h1 = __floats2half2_rn(r.z, r.w);
        uint2 packed = make_uint2(*(unsigned*)&h0, *(unsigned*)&h1);
        *(uint2*)&g_hh[(base + m) * HC + 4 * tid] = packed;

        // partial es/ed, reduced over the 16 lanes of this head group
        float ps = r.x * asv.x + r.y * asv.y + r.z * asv.z + r.w * asv.w;
        float pd = r.x * adv.x + r.y * adv.y + r.z * adv.z + r.w * adv.w;
#pragma unroll
        for (int o = 8; o > 0; o >>= 1) {
            ps += __shfl_xor_sync(0xffffffffu, ps, o);
            pd += __shfl_xor_sync(0xffffffffu, pd, o);
        }
        if ((tid & 15) == 0) {
            g_es[(base + m) * HH + ht] = ps;
            g_ed[(base + m) * HH + ht] = pd;
        }
    }
}

// ---------------------------------------------------------------------------
// Fused softmax-aggregate + normalize + head-mean + bias + gelu.
// One 64-thread block per dst node. Thread t owns channels 4t..4t+3
// (all within head t>>4). Single pass: alpha = exp(e)/sum exp(e)
// (identical analytically to max-shifted form; |e| << 88 here).
// Gather reads fp16 h (half the LTS bytes).
// ---------------------------------------------------------------------------
#define CHUNK 64
__global__ void __launch_bounds__(64) aggregate_kernel(const float* __restrict__ bias) {
    __shared__ int    ss[CHUNK];
    __shared__ float4 ws[CHUNK];
    __shared__ float  outsm[256];

    const int n = blockIdx.x;
    const int t = threadIdx.x;           // 0..63
    const int ht = t >> 4;               // head of channels 4t..4t+3
    const int row0 = g_off[n], row1 = g_off[n + 1];
    const float4 edv = *(const float4*)&g_ed[n * 4];
    const float bv = bias[t];

    float a0 = 0.f, a1 = 0.f, a2 = 0.f, a3 = 0.f, dsum = 0.f;
    for (int base = row0; base < row1; base += CHUNK) {
        int cnt = min(CHUNK, row1 - base);
        if (t < cnt) {
            int s = __ldg(&g_csr[base + t]);
            ss[t] = s;
            float4 esv = __ldg((const float4*)&g_es[s * 4]);
            ws[t] = make_float4(__expf(lrelu(esv.x + edv.x)),
                                __expf(lrelu(esv.y + edv.y)),
                                __expf(lrelu(esv.z + edv.z)),
                                __expf(lrelu(esv.w + edv.w)));
        }
        __syncthreads();
#pragma unroll 2
        for (int e = 0; e < cnt; e++) {
            float wv = ((const float*)&ws[e])[ht];
            uint2 hv = *(const uint2*)&g_hh[ss[e] * HC + 4 * t];
            float2 f0 = __half22float2(*(const __half2*)&hv.x);
            float2 f1 = __half22float2(*(const __half2*)&hv.y);
            a0 += wv * f0.x; a1 += wv * f0.y;
            a2 += wv * f1.x; a3 += wv * f1.y;
            dsum += wv;
        }
        __syncthreads();
    }

    float inv = 1.f / (dsum + 1e-16f);
    *(float4*)&outsm[4 * t] = make_float4(a0 * inv, a1 * inv, a2 * inv, a3 * inv);
    __syncthreads();

    // head mean + bias + gelu (thread t -> channel t)
    float s = 0.25f * (outsm[t] + outsm[64 + t] + outsm[128 + t] + outsm[192 + t]) + bv;
    float tt = tanhf(0.7978845608028654f * (s + 0.044715f * s * s * s));
    g_feat[n * CC + t] = 0.5f * s * (1.f + tt);
}

// ---------------------------------------------------------------------------
// Final FC + sigmoid: out[n] = sigmoid(<feat[n,:], fc_W> + fc_b). Warp per node.
// ---------------------------------------------------------------------------
__global__ void fc_kernel(const float* __restrict__ fcW, const float* __restrict__ fcb,
                          float* __restrict__ out) {
    int gt = blockIdx.x * blockDim.x + threadIdx.x;
    int n = gt >> 5, lane = gt & 31;
    if (n >= NN) return;
    float s = g_feat[n * 64 + lane] * fcW[lane] + g_feat[n * 64 + lane + 32] * fcW[lane + 32];
#pragma unroll
    for (int o = 16; o > 0; o >>= 1) s += __shfl_xor_sync(0xffffffffu, s, o);
    if (lane == 0) out[n] = 1.f / (1.f + __expf(-(s + fcb[0])));
}

// ---------------------------------------------------------------------------

static void run_layer(const float* in, int in_dim, const float* W,
                      const float* a_src, const float* a_dst, const float* b) {
    if (in_dim == 128) gemm_kernel<128><<<NN / TM, 64>>>(in, W, a_src, a_dst);
    else               gemm_kernel<64><<<NN / TM, 64>>>(in, W, a_src, a_dst);
    aggregate_kernel<<<NN, 64>>>(b);
}

extern "C" void kernel_launch(void* const* d_in, const int* in_sizes, int n_in,
                              void* d_out, int out_size) {
    const float* x    = (const float*)d_in[0];
    const int*   ei   = (const int*)d_in[1];
    const float* W1   = (const float*)d_in[2];
    const float* as1  = (const float*)d_in[3];
    const float* ad1  = (const float*)d_in[4];
    const float* b1   = (const float*)d_in[5];
    const float* W2   = (const float*)d_in[6];
    const float* as2  = (const float*)d_in[7];
    const float* ad2  = (const float*)d_in[8];
    const float* b2   = (const float*)d_in[9];
    const float* W3   = (const float*)d_in[10];
    const float* as3  = (const float*)d_in[11];
    const float* ad3  = (const float*)d_in[12];
    const float* b3   = (const float*)d_in[13];
    const float* fcW  = (const float*)d_in[14];
    const float* fcb  = (const float*)d_in[15];

    float* feat_ptr = nullptr;
    cudaGetSymbolAddress((void**)&feat_ptr, g_feat);

    // Build CSR once (edge list identical for all 3 layers)
    hist_zero_kernel<<<(NN + 255) / 256, 256>>>();
    hist_kernel<<<(E2T + 255) / 256, 256>>>(ei);
    scan_kernel<<<1, 1024>>>();
    scatter_kernel<<<(E2T + 255) / 256, 256>>>(ei);

    run_layer(x,        128, W1, as1, ad1, b1);
    run_layer(feat_ptr,  64, W2, as2, ad2, b2);
    run_layer(feat_ptr,  64, W3, as3, ad3, b3);

    fc_kernel<<<(NN * 32 + 255) / 256, 256>>>(fcW, fcb, (float*)d_out);
}

// round 7
// speedup vs baseline: 3.2759x; 1.4886x over previous
#include <cuda_runtime.h>
#include <cuda_fp16.h>

#define NN 50000
#define EE 800000
#define E2T 850000   // EE + NN self loops
#define HH 4
#define CC 64
#define HC 256       // HH*CC

// Scratch (device globals; no allocation allowed)
__device__ __half g_hh[NN * HC];     // fp16 head features for the edge gather
__device__ __half g_feath[NN * CC];  // fp16 layer output after gelu (next GEMM input / fc)
__device__ __half g_wh[128 * 256];   // fp16 copy of current layer's W
__device__ float  g_es[NN * HH];
__device__ float  g_ed[NN * HH];
// CSR (built once; edge list identical across layers)
__device__ int g_cnt[NN];
__device__ int g_off[NN + 1];
__device__ int g_cur[NN];
__device__ int g_csr[E2T];           // src indices grouped by dst

__device__ __forceinline__ float lrelu(float x) { return x >= 0.f ? x : 0.2f * x; }

// ---------------------------------------------------------------------------
// CSR build
// ---------------------------------------------------------------------------
__global__ void hist_zero_kernel() {
    int i = blockIdx.x * blockDim.x + threadIdx.x;
    if (i < NN) g_cnt[i] = 0;
}

__global__ void hist_kernel(const int* __restrict__ ei) {
    int i = blockIdx.x * blockDim.x + threadIdx.x;
    if (i >= E2T) return;
    int dst = (i < EE) ? ei[EE + i] : (i - EE);
    atomicAdd(&g_cnt[dst], 1);
}

// single-block exclusive scan of g_cnt -> g_off (shfl-based)
__global__ void scan_kernel() {
    __shared__ int wsum[32];
    __shared__ int s_total;
    const int tid = threadIdx.x;
    const int lane = tid & 31, wid = tid >> 5;
    int carry = 0;
    for (int base = 0; base < NN; base += 1024) {
        int i = base + tid;
        int v = (i < NN) ? g_cnt[i] : 0;
        int s = v;
#pragma unroll
        for (int o = 1; o < 32; o <<= 1) {
            int t = __shfl_up_sync(0xffffffffu, s, o);
            if (lane >= o) s += t;
        }
        if (lane == 31) wsum[wid] = s;
        __syncthreads();
        if (wid == 0) {
            int w = wsum[lane];
#pragma unroll
            for (int o = 1; o < 32; o <<= 1) {
                int t = __shfl_up_sync(0xffffffffu, w, o);
                if (lane >= o) w += t;
            }
            wsum[lane] = w;
            if (lane == 31) s_total = w;
        }
        __syncthreads();
        int incl = s + (wid ? wsum[wid - 1] : 0);
        if (i < NN) {
            g_off[i] = carry + incl - v;
            g_cur[i] = carry + incl - v;
        }
        carry += s_total;
        __syncthreads();
    }
    if (tid == 0) g_off[NN] = carry;
}

__global__ void scatter_kernel(const int* __restrict__ ei) {
    int i = blockIdx.x * blockDim.x + threadIdx.x;
    if (i >= E2T) return;
    int src, dst;
    if (i < EE) { src = ei[i]; dst = ei[EE + i]; }
    else        { src = i - EE; dst = src; }
    int pos = atomicAdd(&g_cur[dst], 1);
    g_csr[pos] = src;
}

// ---------------------------------------------------------------------------
// W fp32 -> fp16
// ---------------------------------------------------------------------------
__global__ void convw_kernel(const float* __restrict__ W, int n) {
    int i = blockIdx.x * blockDim.x + threadIdx.x;
    if (i < n) g_wh[i] = __float2half(W[i]);
}

// ---------------------------------------------------------------------------
// Tensor-core GEMM + attention epilogue.
// C[NN,256] = A[NN,K] @ W[K,256], fp16 inputs, fp32 accumulate.
// Block: 128 threads / 4 warps; tile M=16, N=256; warp w owns cols [64w,64w+64)
// == head w. mma.sync.m16n8k16.row.col. B via smem + ldmatrix.x4.trans;
// A fragments straight from global (fp32 converted in-register for layer 1).
// Epilogue: fp16 h store + es/ed (from fp32 accums) with 4-lane shfl reduce.
// ---------------------------------------------------------------------------
template <bool F32>
__device__ __forceinline__ unsigned ldA(const void* A, int row, int col, int K) {
    if (F32) {
        float2 f = *(const float2*)((const float*)A + row * K + col);
        __half2 h = __floats2half2_rn(f.x, f.y);
        return *(unsigned*)&h;
    } else {
        return *(const unsigned*)((const __half*)A + row * K + col);
    }
}

template <int K, bool A_FP32>
__global__ void __launch_bounds__(128) hgemm_kernel(const void* __restrict__ Ain,
                                                    const float* __restrict__ a_src,
                                                    const float* __restrict__ a_dst) {
    constexpr int KC = 64;            // k rows staged per chunk
    constexpr int NCH = K / KC;       // 2 (layer 1) or 1 (layers 2-3)
    constexpr int SBS = 264;          // smem stride in halves (528B: rotates banks)
    __shared__ __half sB[KC][SBS];

    const int tid = threadIdx.x;
    const int w = tid >> 5, lane = tid & 31;
    const int g = lane >> 2, tig = lane & 3;
    const int base = blockIdx.x * 16;   // 3125 * 16 == 50000 exactly
    const int n0 = w * 64;

    float c[8][4];
#pragma unroll
    for (int j = 0; j < 8; j++)
#pragma unroll
        for (int q = 0; q < 4; q++) c[j][q] = 0.f;

    for (int ch = 0; ch < NCH; ch++) {
        // stage W chunk [ch*KC, ch*KC+KC) x 256 into sB (uint4 copies)
        for (int idx = tid; idx < KC * 32; idx += 128) {
            int r = idx >> 5, c16 = idx & 31;
            *(uint4*)&sB[r][c16 * 8] =
                *(const uint4*)&g_wh[(ch * KC + r) * 256 + c16 * 8];
        }
        __syncthreads();

#pragma unroll
        for (int kk = 0; kk < KC / 16; kk++) {
            const int kg = ch * KC + kk * 16;
            unsigned a0 = ldA<A_FP32>(Ain, base + g,     kg + 2 * tig,     K);
            unsigned a1 = ldA<A_FP32>(Ain, base + g + 8, kg + 2 * tig,     K);
            unsigned a2 = ldA<A_FP32>(Ain, base + g,     kg + 2 * tig + 8, K);
            unsigned a3 = ldA<A_FP32>(Ain, base + g + 8, kg + 2 * tig + 8, K);
#pragma unroll
            for (int jp = 0; jp < 4; jp++) {
                // B fragments for n-cols [n0+16jp, n0+16jp+16)
                unsigned b0, b1, b2, b3;
                unsigned addr = (unsigned)__cvta_generic_to_shared(
                    &sB[kk * 16 + (lane & 15)][n0 + jp * 16 + (lane >> 4) * 8]);
                asm volatile(
                    "ldmatrix.sync.aligned.m8n8.x4.trans.shared.b16 {%0,%1,%2,%3}, [%4];"
                    : "=r"(b0), "=r"(b1), "=r"(b2), "=r"(b3) : "r"(addr));
                asm volatile(
                    "mma.sync.aligned.m16n8k16.row.col.f32.f16.f16.f32 "
                    "{%0,%1,%2,%3}, {%4,%5,%6,%7}, {%8,%9}, {%0,%1,%2,%3};"
                    : "+f"(c[2*jp][0]), "+f"(c[2*jp][1]), "+f"(c[2*jp][2]), "+f"(c[2*jp][3])
                    : "r"(a0), "r"(a1), "r"(a2), "r"(a3), "r"(b0), "r"(b1));
                asm volatile(
                    "mma.sync.aligned.m16n8k16.row.col.f32.f16.f16.f32 "
                    "{%0,%1,%2,%3}, {%4,%5,%6,%7}, {%8,%9}, {%0,%1,%2,%3};"
                    : "+f"(c[2*jp+1][0]), "+f"(c[2*jp+1][1]), "+f"(c[2*jp+1][2]), "+f"(c[2*jp+1][3])
                    : "r"(a0), "r"(a1), "r"(a2), "r"(a3), "r"(b2), "r"(b3));
            }
        }
        __syncthreads();
    }

    // Epilogue: store fp16 h; es/ed partials from fp32 accumulators.
    float ps0 = 0.f, pd0 = 0.f, ps1 = 0.f, pd1 = 0.f;
#pragma unroll
    for (int j = 0; j < 8; j++) {
        int col = n0 + 8 * j + 2 * tig;  // flat channel index == h*64 + c
        __half2 h0 = __floats2half2_rn(c[j][0], c[j][1]);
        __half2 h1 = __floats2half2_rn(c[j][2], c[j][3]);
        *(__half2*)&g_hh[(base + g) * HC + col]     = h0;
        *(__half2*)&g_hh[(base + g + 8) * HC + col] = h1;
        float2 as2 = *(const float2*)&a_src[col];
        float2 ad2 = *(const float2*)&a_dst[col];
        ps0 += c[j][0] * as2.x + c[j][1] * as2.y;
        pd0 += c[j][0] * ad2.x + c[j][1] * ad2.y;
        ps1 += c[j][2] * as2.x + c[j][3] * as2.y;
        pd1 += c[j][2] * ad2.x + c[j][3] * ad2.y;
    }
#pragma unroll
    for (int o = 1; o <= 2; o <<= 1) {
        ps0 += __shfl_xor_sync(0xffffffffu, ps0, o);
        pd0 += __shfl_xor_sync(0xffffffffu, pd0, o);
        ps1 += __shfl_xor_sync(0xffffffffu, ps1, o);
        pd1 += __shfl_xor_sync(0xffffffffu, pd1, o);
    }
    if (tig == 0) {
        g_es[(base + g) * HH + w]     = ps0;
        g_ed[(base + g) * HH + w]     = pd0;
        g_es[(base + g + 8) * HH + w] = ps1;
        g_ed[(base + g + 8) * HH + w] = pd1;
    }
}

// ---------------------------------------------------------------------------
// Fused softmax-aggregate + normalize + head-mean + bias + gelu -> fp16 out.
// One 64-thread block per dst node; thread t owns channels 4t..4t+3 (head t>>4).
// Single pass: alpha = exp(e)/sum exp(e) (identical analytically; |e| << 88).
// ---------------------------------------------------------------------------
#define CHUNK 64
__global__ void __launch_bounds__(64) aggregate_kernel(const float* __restrict__ bias) {
    __shared__ int    ss[CHUNK];
    __shared__ float4 ws[CHUNK];
    __shared__ float  outsm[256];

    const int n = blockIdx.x;
    const int t = threadIdx.x;           // 0..63
    const int ht = t >> 4;               // head of channels 4t..4t+3
    const int row0 = g_off[n], row1 = g_off[n + 1];
    const float4 edv = *(const float4*)&g_ed[n * 4];
    const float bv = bias[t];

    float a0 = 0.f, a1 = 0.f, a2 = 0.f, a3 = 0.f, dsum = 0.f;
    for (int base = row0; base < row1; base += CHUNK) {
        int cnt = min(CHUNK, row1 - base);
        if (t < cnt) {
            int s = __ldg(&g_csr[base + t]);
            ss[t] = s;
            float4 esv = __ldg((const float4*)&g_es[s * 4]);
            ws[t] = make_float4(__expf(lrelu(esv.x + edv.x)),
                                __expf(lrelu(esv.y + edv.y)),
                                __expf(lrelu(esv.z + edv.z)),
                                __expf(lrelu(esv.w + edv.w)));
        }
        __syncthreads();
#pragma unroll 4
        for (int e = 0; e < cnt; e++) {
            float wv = ((const float*)&ws[e])[ht];
            uint2 hv = *(const uint2*)&g_hh[ss[e] * HC + 4 * t];
            float2 f0 = __half22float2(*(const __half2*)&hv.x);
            float2 f1 = __half22float2(*(const __half2*)&hv.y);
            a0 += wv * f0.x; a1 += wv * f0.y;
            a2 += wv * f1.x; a3 += wv * f1.y;
            dsum += wv;
        }
        __syncthreads();
    }

    float inv = 1.f / (dsum + 1e-16f);
    *(float4*)&outsm[4 * t] = make_float4(a0 * inv, a1 * inv, a2 * inv, a3 * inv);
    __syncthreads();

    // head mean + bias + gelu (thread t -> channel t), fp16 output
    float s = 0.25f * (outsm[t] + outsm[64 + t] + outsm[128 + t] + outsm[192 + t]) + bv;
    float tt = tanhf(0.7978845608028654f * (s + 0.044715f * s * s * s));
    g_feath[n * CC + t] = __float2half(0.5f * s * (1.f + tt));
}

// ---------------------------------------------------------------------------
// Final FC + sigmoid: out[n] = sigmoid(<feat[n,:], fc_W> + fc_b). Warp per node.
// ---------------------------------------------------------------------------
__global__ void fc_kernel(const float* __restrict__ fcW, const float* __restrict__ fcb,
                          float* __restrict__ out) {
    int gt = blockIdx.x * blockDim.x + threadIdx.x;
    int n = gt >> 5, lane = gt & 31;
    if (n >= NN) return;
    float f0 = __half2float(g_feath[n * 64 + lane]);
    float f1 = __half2float(g_feath[n * 64 + lane + 32]);
    float s = f0 * fcW[lane] + f1 * fcW[lane + 32];
#pragma unroll
    for (int o = 16; o > 0; o >>= 1) s += __shfl_xor_sync(0xffffffffu, s, o);
    if (lane == 0) out[n] = 1.f / (1.f + __expf(-(s + fcb[0])));
}

// ---------------------------------------------------------------------------

template <int K, bool A_FP32>
static void run_layer(const void* in, const float* W,
                      const float* a_src, const float* a_dst, const float* b) {
    convw_kernel<<<(K * 256 + 255) / 256, 256>>>(W, K * 256);
    hgemm_kernel<K, A_FP32><<<NN / 16, 128>>>(in, a_src, a_dst);
    aggregate_kernel<<<NN, 64>>>(b);
}

extern "C" void kernel_launch(void* const* d_in, const int* in_sizes, int n_in,
                              void* d_out, int out_size) {
    const float* x    = (const float*)d_in[0];
    const int*   ei   = (const int*)d_in[1];
    const float* W1   = (const float*)d_in[2];
    const float* as1  = (const float*)d_in[3];
    const float* ad1  = (const float*)d_in[4];
    const float* b1   = (const float*)d_in[5];
    const float* W2   = (const float*)d_in[6];
    const float* as2  = (const float*)d_in[7];
    const float* ad2  = (const float*)d_in[8];
    const float* b2   = (const float*)d_in[9];
    const float* W3   = (const float*)d_in[10];
    const float* as3  = (const float*)d_in[11];
    const float* ad3  = (const float*)d_in[12];
    const float* b3   = (const float*)d_in[13];
    const float* fcW  = (const float*)d_in[14];
    const float* fcb  = (const float*)d_in[15];

    __half* feath_ptr = nullptr;
    cudaGetSymbolAddress((void**)&feath_ptr, g_feath);

    // Build CSR once (edge list identical for all 3 layers)
    hist_zero_kernel<<<(NN + 255) / 256, 256>>>();
    hist_kernel<<<(E2T + 255) / 256, 256>>>(ei);
    scan_kernel<<<1, 1024>>>();
    scatter_kernel<<<(E2T + 255) / 256, 256>>>(ei);

    run_layer<128, true>(x,         W1, as1, ad1, b1);
    run_layer<64, false>(feath_ptr, W2, as2, ad2, b2);
    run_layer<64, false>(feath_ptr, W3, as3, ad3, b3);

    fc_kernel<<<(NN * 32 + 255) / 256, 256>>>(fcW, fcb, (float*)d_out);
}

// round 8
// speedup vs baseline: 3.2954x; 1.0060x over previous
#include <cuda_runtime.h>
#include <cuda_fp16.h>

#define NN 50000
#define EE 800000
#define E2T 850000   // EE + NN self loops
#define HH 4
#define CC 64
#define HC 256       // HH*CC

// Scratch (device globals; no allocation allowed)
__device__ __half g_hh[NN * HC];     // fp16 head features for the edge gather
__device__ __half g_feath[NN * CC];  // fp16 layer output after gelu (next GEMM input / fc)
__device__ __half g_wh[128 * 256];   // fp16 copy of current layer's W
__device__ float  g_es[NN * HH];
__device__ float  g_ed[NN * HH];
// CSR (built once; edge list identical across layers)
__device__ int g_cnt[NN];
__device__ int g_off[NN + 1];
__device__ int g_cur[NN];
__device__ int g_csr[E2T];           // src indices grouped by dst

__device__ __forceinline__ float lrelu(float x) { return x >= 0.f ? x : 0.2f * x; }

// ---------------------------------------------------------------------------
// CSR build
// ---------------------------------------------------------------------------
__global__ void hist_zero_kernel() {
    int i = blockIdx.x * blockDim.x + threadIdx.x;
    if (i < NN) g_cnt[i] = 0;
}

__global__ void hist_kernel(const int* __restrict__ ei) {
    int i = blockIdx.x * blockDim.x + threadIdx.x;
    if (i >= E2T) return;
    int dst = (i < EE) ? ei[EE + i] : (i - EE);
    atomicAdd(&g_cnt[dst], 1);
}

// single-block exclusive scan of g_cnt -> g_off (shfl-based)
__global__ void scan_kernel() {
    __shared__ int wsum[32];
    __shared__ int s_total;
    const int tid = threadIdx.x;
    const int lane = tid & 31, wid = tid >> 5;
    int carry = 0;
    for (int base = 0; base < NN; base += 1024) {
        int i = base + tid;
        int v = (i < NN) ? g_cnt[i] : 0;
        int s = v;
#pragma unroll
        for (int o = 1; o < 32; o <<= 1) {
            int t = __shfl_up_sync(0xffffffffu, s, o);
            if (lane >= o) s += t;
        }
        if (lane == 31) wsum[wid] = s;
        __syncthreads();
        if (wid == 0) {
            int w = wsum[lane];
#pragma unroll
            for (int o = 1; o < 32; o <<= 1) {
                int t = __shfl_up_sync(0xffffffffu, w, o);
                if (lane >= o) w += t;
            }
            wsum[lane] = w;
            if (lane == 31) s_total = w;
        }
        __syncthreads();
        int incl = s + (wid ? wsum[wid - 1] : 0);
        if (i < NN) {
            g_off[i] = carry + incl - v;
            g_cur[i] = carry + incl - v;
        }
        carry += s_total;
        __syncthreads();
    }
    if (tid == 0) g_off[NN] = carry;
}

__global__ void scatter_kernel(const int* __restrict__ ei) {
    int i = blockIdx.x * blockDim.x + threadIdx.x;
    if (i >= E2T) return;
    int src, dst;
    if (i < EE) { src = ei[i]; dst = ei[EE + i]; }
    else        { src = i - EE; dst = src; }
    int pos = atomicAdd(&g_cur[dst], 1);
    g_csr[pos] = src;
}

// ---------------------------------------------------------------------------
// W fp32 -> fp16
// ---------------------------------------------------------------------------
__global__ void convw_kernel(const float* __restrict__ W, int n) {
    int i = blockIdx.x * blockDim.x + threadIdx.x;
    if (i < n) g_wh[i] = __float2half(W[i]);
}

// ---------------------------------------------------------------------------
// Tensor-core GEMM + attention epilogue.
// C[NN,256] = A[NN,K] @ W[K,256], fp16 inputs, fp32 accumulate.
// Block: 128 threads / 4 warps; tile M=16, N=256; warp w owns cols [64w,64w+64)
// == head w. mma.sync.m16n8k16.row.col. B via smem + ldmatrix.x4.trans;
// A fragments straight from global (fp32 converted in-register for layer 1).
// Epilogue: fp16 h store + es/ed (from fp32 accums) with 4-lane shfl reduce.
// ---------------------------------------------------------------------------
template <bool F32>
__device__ __forceinline__ unsigned ldA(const void* A, int row, int col, int K) {
    if (F32) {
        float2 f = *(const float2*)((const float*)A + row * K + col);
        __half2 h = __floats2half2_rn(f.x, f.y);
        return *(unsigned*)&h;
    } else {
        return *(const unsigned*)((const __half*)A + row * K + col);
    }
}

template <int K, bool A_FP32>
__global__ void __launch_bounds__(128) hgemm_kernel(const void* __restrict__ Ain,
                                                    const float* __restrict__ a_src,
                                                    const float* __restrict__ a_dst) {
    constexpr int KC = 64;            // k rows staged per chunk
    constexpr int NCH = K / KC;       // 2 (layer 1) or 1 (layers 2-3)
    constexpr int SBS = 264;          // smem stride in halves (528B: rotates banks)
    __shared__ __half sB[KC][SBS];

    const int tid = threadIdx.x;
    const int w = tid >> 5, lane = tid & 31;
    const int g = lane >> 2, tig = lane & 3;
    const int base = blockIdx.x * 16;   // 3125 * 16 == 50000 exactly
    const int n0 = w * 64;

    float c[8][4];
#pragma unroll
    for (int j = 0; j < 8; j++)
#pragma unroll
        for (int q = 0; q < 4; q++) c[j][q] = 0.f;

    for (int ch = 0; ch < NCH; ch++) {
        // stage W chunk [ch*KC, ch*KC+KC) x 256 into sB (uint4 copies)
        for (int idx = tid; idx < KC * 32; idx += 128) {
            int r = idx >> 5, c16 = idx & 31;
            *(uint4*)&sB[r][c16 * 8] =
                *(const uint4*)&g_wh[(ch * KC + r) * 256 + c16 * 8];
        }
        __syncthreads();

#pragma unroll
        for (int kk = 0; kk < KC / 16; kk++) {
            const int kg = ch * KC + kk * 16;
            unsigned a0 = ldA<A_FP32>(Ain, base + g,     kg + 2 * tig,     K);
            unsigned a1 = ldA<A_FP32>(Ain, base + g + 8, kg + 2 * tig,     K);
            unsigned a2 = ldA<A_FP32>(Ain, base + g,     kg + 2 * tig + 8, K);
            unsigned a3 = ldA<A_FP32>(Ain, base + g + 8, kg + 2 * tig + 8, K);
#pragma unroll
            for (int jp = 0; jp < 4; jp++) {
                // B fragments for n-cols [n0+16jp, n0+16jp+16)
                unsigned b0, b1, b2, b3;
                unsigned addr = (unsigned)__cvta_generic_to_shared(
                    &sB[kk * 16 + (lane & 15)][n0 + jp * 16 + (lane >> 4) * 8]);
                asm volatile(
                    "ldmatrix.sync.aligned.m8n8.x4.trans.shared.b16 {%0,%1,%2,%3}, [%4];"
                    : "=r"(b0), "=r"(b1), "=r"(b2), "=r"(b3) : "r"(addr));
                asm volatile(
                    "mma.sync.aligned.m16n8k16.row.col.f32.f16.f16.f32 "
                    "{%0,%1,%2,%3}, {%4,%5,%6,%7}, {%8,%9}, {%0,%1,%2,%3};"
                    : "+f"(c[2*jp][0]), "+f"(c[2*jp][1]), "+f"(c[2*jp][2]), "+f"(c[2*jp][3])
                    : "r"(a0), "r"(a1), "r"(a2), "r"(a3), "r"(b0), "r"(b1));
                asm volatile(
                    "mma.sync.aligned.m16n8k16.row.col.f32.f16.f16.f32 "
                    "{%0,%1,%2,%3}, {%4,%5,%6,%7}, {%8,%9}, {%0,%1,%2,%3};"
                    : "+f"(c[2*jp+1][0]), "+f"(c[2*jp+1][1]), "+f"(c[2*jp+1][2]), "+f"(c[2*jp+1][3])
                    : "r"(a0), "r"(a1), "r"(a2), "r"(a3), "r"(b2), "r"(b3));
            }
        }
        __syncthreads();
    }

    // Epilogue: store fp16 h; es/ed partials from fp32 accumulators.
    float ps0 = 0.f, pd0 = 0.f, ps1 = 0.f, pd1 = 0.f;
#pragma unroll
    for (int j = 0; j < 8; j++) {
        int col = n0 + 8 * j + 2 * tig;  // flat channel index == h*64 + c
        __half2 h0 = __floats2half2_rn(c[j][0], c[j][1]);
        __half2 h1 = __floats2half2_rn(c[j][2], c[j][3]);
        *(__half2*)&g_hh[(base + g) * HC + col]     = h0;
        *(__half2*)&g_hh[(base + g + 8) * HC + col] = h1;
        float2 as2 = *(const float2*)&a_src[col];
        float2 ad2 = *(const float2*)&a_dst[col];
        ps0 += c[j][0] * as2.x + c[j][1] * as2.y;
        pd0 += c[j][0] * ad2.x + c[j][1] * ad2.y;
        ps1 += c[j][2] * as2.x + c[j][3] * as2.y;
        pd1 += c[j][2] * ad2.x + c[j][3] * ad2.y;
    }
#pragma unroll
    for (int o = 1; o <= 2; o <<= 1) {
        ps0 += __shfl_xor_sync(0xffffffffu, ps0, o);
        pd0 += __shfl_xor_sync(0xffffffffu, pd0, o);
        ps1 += __shfl_xor_sync(0xffffffffu, ps1, o);
        pd1 += __shfl_xor_sync(0xffffffffu, pd1, o);
    }
    if (tig == 0) {
        g_es[(base + g) * HH + w]     = ps0;
        g_ed[(base + g) * HH + w]     = pd0;
        g_es[(base + g + 8) * HH + w] = ps1;
        g_ed[(base + g + 8) * HH + w] = pd1;
    }
}

// ---------------------------------------------------------------------------
// Fused softmax-aggregate + normalize + head-mean + bias + gelu -> fp16 out.
// Warp per dst node (8 nodes per 256-thread block). Lane t owns channels
// 8t..8t+7 (one LDG.128/edge). Weights staged per-warp in smem, __syncwarp only.
// Single pass: alpha = exp(e)/sum exp(e) (analytically identical; |e| << 88).
// Head-mean via shfl_xor(8) + shfl_xor(16).
// ---------------------------------------------------------------------------
__global__ void __launch_bounds__(256) aggregate_kernel(const float* __restrict__ bias) {
    __shared__ int    ss[8][32];
    __shared__ float4 ws[8][32];

    const int wid = threadIdx.x >> 5;
    const int lid = threadIdx.x & 31;
    const int n = blockIdx.x * 8 + wid;   // NN == 6250 * 8
    const int head = lid >> 3;            // head of channels 8*lid..8*lid+7

    const int row0 = g_off[n], row1 = g_off[n + 1];
    const float4 edv = *(const float4*)&g_ed[n * 4];

    float acc[8] = {0.f, 0.f, 0.f, 0.f, 0.f, 0.f, 0.f, 0.f};
    float dsum = 0.f;

    for (int base = row0; base < row1; base += 32) {
        int cnt = min(32, row1 - base);
        if (lid < cnt) {
            int s = __ldg(&g_csr[base + lid]);
            ss[wid][lid] = s * HC;
            float4 esv = __ldg((const float4*)&g_es[s * 4]);
            ws[wid][lid] = make_float4(__expf(lrelu(esv.x + edv.x)),
                                       __expf(lrelu(esv.y + edv.y)),
                                       __expf(lrelu(esv.z + edv.z)),
                                       __expf(lrelu(esv.w + edv.w)));
        }
        __syncwarp();
#pragma unroll 4
        for (int e = 0; e < cnt; e++) {
            float wv = ((const float*)&ws[wid][e])[head];
            uint4 hv = *(const uint4*)&g_hh[ss[wid][e] + 8 * lid];
            float2 f0 = __half22float2(*(const __half2*)&hv.x);
            float2 f1 = __half22float2(*(const __half2*)&hv.y);
            float2 f2 = __half22float2(*(const __half2*)&hv.z);
            float2 f3 = __half22float2(*(const __half2*)&hv.w);
            acc[0] += wv * f0.x; acc[1] += wv * f0.y;
            acc[2] += wv * f1.x; acc[3] += wv * f1.y;
            acc[4] += wv * f2.x; acc[5] += wv * f2.y;
            acc[6] += wv * f3.x; acc[7] += wv * f3.y;
            dsum += wv;
        }
        __syncwarp();
    }

    // normalize by this head's denominator, then mean across heads via shfl
    float inv = 1.f / (dsum + 1e-16f);
#pragma unroll
    for (int i = 0; i < 8; i++) {
        acc[i] *= inv;
        acc[i] += __shfl_xor_sync(0xffffffffu, acc[i], 8);
        acc[i] += __shfl_xor_sync(0xffffffffu, acc[i], 16);
    }
    // lanes 0..7 now hold head-sums for channels 8*lid..8*lid+7
    if (lid < 8) {
        __half2 outh[4];
#pragma unroll
        for (int i = 0; i < 8; i += 2) {
            float s0 = 0.25f * acc[i]     + bias[8 * lid + i];
            float s1 = 0.25f * acc[i + 1] + bias[8 * lid + i + 1];
            float t0 = tanhf(0.7978845608028654f * (s0 + 0.044715f * s0 * s0 * s0));
            float t1 = tanhf(0.7978845608028654f * (s1 + 0.044715f * s1 * s1 * s1));
            outh[i >> 1] = __floats2half2_rn(0.5f * s0 * (1.f + t0),
                                             0.5f * s1 * (1.f + t1));
        }
        *(uint4*)&g_feath[n * CC + 8 * lid] = *(uint4*)outh;
    }
}

// ---------------------------------------------------------------------------
// Final FC + sigmoid: out[n] = sigmoid(<feat[n,:], fc_W> + fc_b). Warp per node.
// ---------------------------------------------------------------------------
__global__ void fc_kernel(const float* __restrict__ fcW, const float* __restrict__ fcb,
                          float* __restrict__ out) {
    int gt = blockIdx.x * blockDim.x + threadIdx.x;
    int n = gt >> 5, lane = gt & 31;
    if (n >= NN) return;
    float f0 = __half2float(g_feath[n * 64 + lane]);
    float f1 = __half2float(g_feath[n * 64 + lane + 32]);
    float s = f0 * fcW[lane] + f1 * fcW[lane + 32];
#pragma unroll
    for (int o = 16; o > 0; o >>= 1) s += __shfl_xor_sync(0xffffffffu, s, o);
    if (lane == 0) out[n] = 1.f / (1.f + __expf(-(s + fcb[0])));
}

// ---------------------------------------------------------------------------

template <int K, bool A_FP32>
static void run_layer(const void* in, const float* W,
                      const float* a_src, const float* a_dst, const float* b) {
    convw_kernel<<<(K * 256 + 255) / 256, 256>>>(W, K * 256);
    hgemm_kernel<K, A_FP32><<<NN / 16, 128>>>(in, a_src, a_dst);
    aggregate_kernel<<<NN / 8, 256>>>(b);
}

extern "C" void kernel_launch(void* const* d_in, const int* in_sizes, int n_in,
                              void* d_out, int out_size) {
    const float* x    = (const float*)d_in[0];
    const int*   ei   = (const int*)d_in[1];
    const float* W1   = (const float*)d_in[2];
    const float* as1  = (const float*)d_in[3];
    const float* ad1  = (const float*)d_in[4];
    const float* b1   = (const float*)d_in[5];
    const float* W2   = (const float*)d_in[6];
    const float* as2  = (const float*)d_in[7];
    const float* ad2  = (const float*)d_in[8];
    const float* b2   = (const float*)d_in[9];
    const float* W3   = (const float*)d_in[10];
    const float* as3  = (const float*)d_in[11];
    const float* ad3  = (const float*)d_in[12];
    const float* b3   = (const float*)d_in[13];
    const float* fcW  = (const float*)d_in[14];
    const float* fcb  = (const float*)d_in[15];

    __half* feath_ptr = nullptr;
    cudaGetSymbolAddress((void**)&feath_ptr, g_feath);

    // Build CSR once (edge list identical for all 3 layers)
    hist_zero_kernel<<<(NN + 255) / 256, 256>>>();
    hist_kernel<<<(E2T + 255) / 256, 256>>>(ei);
    scan_kernel<<<1, 1024>>>();
    scatter_kernel<<<(E2T + 255) / 256, 256>>>(ei);

    run_layer<128, true>(x,         W1, as1, ad1, b1);
    run_layer<64, false>(feath_ptr, W2, as2, ad2, b2);
    run_layer<64, false>(feath_ptr, W3, as3, ad3, b3);

    fc_kernel<<<(NN * 32 + 255) / 256, 256>>>(fcW, fcb, (float*)d_out);
}

// round 9
// speedup vs baseline: 3.8156x; 1.1578x over previous
#include <cuda_runtime.h>
#include <cuda_fp16.h>

#define NN 50000
#define EE 800000
#define E2T 850000   // EE + NN self loops
#define HH 4
#define CC 64
#define HC 256       // HH*CC

// Scratch (device globals; no allocation allowed)
__device__ __half g_hh[NN * HC];     // fp16 head features for the edge gather
__device__ __half g_feath[NN * CC];  // fp16 layer output after gelu (next GEMM input)
__device__ __half g_wh[128 * 256];   // fp16 copy of current layer's W
__device__ float  g_es[NN * HH];
__device__ float  g_ed[NN * HH];
// CSR (built once; edge list identical across layers)
__device__ int g_cnt[NN];
__device__ int g_off[NN + 1];
__device__ int g_cur[NN];
__device__ int g_csr[E2T];           // src indices grouped by dst

__device__ __forceinline__ float lrelu(float x) { return x >= 0.f ? x : 0.2f * x; }

// ---------------------------------------------------------------------------
// CSR build
// ---------------------------------------------------------------------------
__global__ void hist_kernel(const int* __restrict__ ei) {
    int i = blockIdx.x * blockDim.x + threadIdx.x;
    if (i >= E2T) return;
    int dst = (i < EE) ? ei[EE + i] : (i - EE);
    atomicAdd(&g_cnt[dst], 1);
}

// single-block exclusive scan of g_cnt -> g_off/g_cur, int4-vectorized
__global__ void scan_kernel() {
    __shared__ int wsum[32];
    __shared__ int s_total;
    const int tid = threadIdx.x;
    const int lane = tid & 31, wid = tid >> 5;
    constexpr int N4 = NN / 4;  // 12500
    int carry = 0;
    for (int b4 = 0; b4 < N4; b4 += 1024) {
        int i4 = b4 + tid;
        int4 v = make_int4(0, 0, 0, 0);
        if (i4 < N4) v = ((const int4*)g_cnt)[i4];
        int tsum = v.x + v.y + v.z + v.w;
        int s = tsum;
#pragma unroll
        for (int o = 1; o < 32; o <<= 1) {
            int t = __shfl_up_sync(0xffffffffu, s, o);
            if (lane >= o) s += t;
        }
        if (lane == 31) wsum[wid] = s;
        __syncthreads();
        if (wid == 0) {
            int w = wsum[lane];
#pragma unroll
            for (int o = 1; o < 32; o <<= 1) {
                int t = __shfl_up_sync(0xffffffffu, w, o);
                if (lane >= o) w += t;
            }
            wsum[lane] = w;
            if (lane == 31) s_total = w;
        }
        __syncthreads();
        int excl = s - tsum + (wid ? wsum[wid - 1] : 0) + carry;
        if (i4 < N4) {
            int4 o;
            o.x = excl;
            o.y = o.x + v.x;
            o.z = o.y + v.y;
            o.w = o.z + v.z;
            ((int4*)g_off)[i4] = o;
            ((int4*)g_cur)[i4] = o;
        }
        carry += s_total;
        __syncthreads();
    }
    if (tid == 0) g_off[NN] = carry;
}

__global__ void scatter_kernel(const int* __restrict__ ei) {
    int i = blockIdx.x * blockDim.x + threadIdx.x;
    if (i >= E2T) return;
    int src, dst;
    if (i < EE) { src = ei[i]; dst = ei[EE + i]; }
    else        { src = i - EE; dst = src; }
    int pos = atomicAdd(&g_cur[dst], 1);
    g_csr[pos] = src;
}

// ---------------------------------------------------------------------------
// W fp32 -> fp16
// ---------------------------------------------------------------------------
__global__ void convw_kernel(const float* __restrict__ W, int n) {
    int i = blockIdx.x * blockDim.x + threadIdx.x;
    if (i < n) g_wh[i] = __float2half(W[i]);
}

// ---------------------------------------------------------------------------
// Tensor-core GEMM + attention epilogue.  M=32 tile (predicated tail).
// C[NN,256] = A[NN,K] @ W[K,256], fp16 in, fp32 accum.
// 128 threads / 4 warps; warp w owns cols [64w,64w+64) == head w, all 32 rows.
// mma.sync.m16n8k16.row.col; B via smem + ldmatrix.x4.trans.
// Epilogue: fp16 h store + es/ed from fp32 accums, 4-lane shfl reduce.
// ---------------------------------------------------------------------------
template <bool F32>
__device__ __forceinline__ unsigned ldA(const void* A, int row, int col, int K, bool valid) {
    if (!valid) return 0u;
    if (F32) {
        float2 f = *(const float2*)((const float*)A + row * K + col);
        __half2 h = __floats2half2_rn(f.x, f.y);
        return *(unsigned*)&h;
    } else {
        return *(const unsigned*)((const __half*)A + row * K + col);
    }
}

template <int K, bool A_FP32>
__global__ void __launch_bounds__(128) hgemm_kernel(const void* __restrict__ Ain,
                                                    const float* __restrict__ a_src,
                                                    const float* __restrict__ a_dst) {
    constexpr int KC = 64;            // k rows staged per chunk
    constexpr int NCH = K / KC;       // 2 (layer 1) or 1 (layers 2-3)
    constexpr int SBS = 264;          // smem stride in halves
    __shared__ __half sB[KC][SBS];

    const int tid = threadIdx.x;
    const int w = tid >> 5, lane = tid & 31;
    const int g = lane >> 2, tig = lane & 3;
    const int base = blockIdx.x * 32;
    const int n0 = w * 64;

    const int r0 = base + g,      r1 = base + g + 8;
    const int r2 = base + g + 16, r3 = base + g + 24;
    const bool v2 = r2 < NN, v3 = r3 < NN;

    float c[2][8][4];
#pragma unroll
    for (int rg = 0; rg < 2; rg++)
#pragma unroll
        for (int j = 0; j < 8; j++)
#pragma unroll
            for (int q = 0; q < 4; q++) c[rg][j][q] = 0.f;

    for (int ch = 0; ch < NCH; ch++) {
        for (int idx = tid; idx < KC * 32; idx += 128) {
            int r = idx >> 5, c16 = idx & 31;
            *(uint4*)&sB[r][c16 * 8] =
                *(const uint4*)&g_wh[(ch * KC + r) * 256 + c16 * 8];
        }
        __syncthreads();

#pragma unroll
        for (int kk = 0; kk < KC / 16; kk++) {
            const int kg = ch * KC + kk * 16;
            unsigned a0 = ldA<A_FP32>(Ain, r0, kg + 2 * tig,     K, true);
            unsigned a1 = ldA<A_FP32>(Ain, r1, kg + 2 * tig,     K, true);
            unsigned a2 = ldA<A_FP32>(Ain, r0, kg + 2 * tig + 8, K, true);
            unsigned a3 = ldA<A_FP32>(Ain, r1, kg + 2 * tig + 8, K, true);
            unsigned a4 = ldA<A_FP32>(Ain, r2, kg + 2 * tig,     K, v2);
            unsigned a5 = ldA<A_FP32>(Ain, r3, kg + 2 * tig,     K, v3);
            unsigned a6 = ldA<A_FP32>(Ain, r2, kg + 2 * tig + 8, K, v2);
            unsigned a7 = ldA<A_FP32>(Ain, r3, kg + 2 * tig + 8, K, v3);
#pragma unroll
            for (int jp = 0; jp < 4; jp++) {
                unsigned b0, b1, b2, b3;
                unsigned addr = (unsigned)__cvta_generic_to_shared(
                    &sB[kk * 16 + (lane & 15)][n0 + jp * 16 + (lane >> 4) * 8]);
                asm volatile(
                    "ldmatrix.sync.aligned.m8n8.x4.trans.shared.b16 {%0,%1,%2,%3}, [%4];"
                    : "=r"(b0), "=r"(b1), "=r"(b2), "=r"(b3) : "r"(addr));
                asm volatile(
                    "mma.sync.aligned.m16n8k16.row.col.f32.f16.f16.f32 "
                    "{%0,%1,%2,%3}, {%4,%5,%6,%7}, {%8,%9}, {%0,%1,%2,%3};"
                    : "+f"(c[0][2*jp][0]), "+f"(c[0][2*jp][1]), "+f"(c[0][2*jp][2]), "+f"(c[0][2*jp][3])
                    : "r"(a0), "r"(a1), "r"(a2), "r"(a3), "r"(b0), "r"(b1));
                asm volatile(
                    "mma.sync.aligned.m16n8k16.row.col.f32.f16.f16.f32 "
                    "{%0,%1,%2,%3}, {%4,%5,%6,%7}, {%8,%9}, {%0,%1,%2,%3};"
                    : "+f"(c[0][2*jp+1][0]), "+f"(c[0][2*jp+1][1]), "+f"(c[0][2*jp+1][2]), "+f"(c[0][2*jp+1][3])
                    : "r"(a0), "r"(a1), "r"(a2), "r"(a3), "r"(b2), "r"(b3));
                asm volatile(
                    "mma.sync.aligned.m16n8k16.row.col.f32.f16.f16.f32 "
                    "{%0,%1,%2,%3}, {%4,%5,%6,%7}, {%8,%9}, {%0,%1,%2,%3};"
                    : "+f"(c[1][2*jp][0]), "+f"(c[1][2*jp][1]), "+f"(c[1][2*jp][2]), "+f"(c[1][2*jp][3])
                    : "r"(a4), "r"(a5), "r"(a6), "r"(a7), "r"(b0), "r"(b1));
                asm volatile(
                    "mma.sync.aligned.m16n8k16.row.col.f32.f16.f16.f32 "
                    "{%0,%1,%2,%3}, {%4,%5,%6,%7}, {%8,%9}, {%0,%1,%2,%3};"
                    : "+f"(c[1][2*jp+1][0]), "+f"(c[1][2*jp+1][1]), "+f"(c[1][2*jp+1][2]), "+f"(c[1][2*jp+1][3])
                    : "r"(a4), "r"(a5), "r"(a6), "r"(a7), "r"(b2), "r"(b3));
            }
        }
        __syncthreads();
    }

    // Epilogue: ps/pd[0]=row r0, [1]=r1, [2]=r2, [3]=r3
    float ps[4] = {0.f, 0.f, 0.f, 0.f};
    float pd[4] = {0.f, 0.f, 0.f, 0.f};
#pragma unroll
    for (int j = 0; j < 8; j++) {
        int col = n0 + 8 * j + 2 * tig;
        float2 as2 = *(const float2*)&a_src[col];
        float2 ad2 = *(const float2*)&a_dst[col];
#pragma unroll
        for (int rg = 0; rg < 2; rg++) {
            int rowA = base + 16 * rg + g, rowB = rowA + 8;
            __half2 h0 = __floats2half2_rn(c[rg][j][0], c[rg][j][1]);
            __half2 h1 = __floats2half2_rn(c[rg][j][2], c[rg][j][3]);
            if (rowA < NN) *(__half2*)&g_hh[rowA * HC + col] = h0;
            if (rowB < NN) *(__half2*)&g_hh[rowB * HC + col] = h1;
            ps[2*rg]   += c[rg][j][0] * as2.x + c[rg][j][1] * as2.y;
            pd[2*rg]   += c[rg][j][0] * ad2.x + c[rg][j][1] * ad2.y;
            ps[2*rg+1] += c[rg][j][2] * as2.x + c[rg][j][3] * as2.y;
            pd[2*rg+1] += c[rg][j][2] * ad2.x + c[rg][j][3] * ad2.y;
        }
    }
#pragma unroll
    for (int o = 1; o <= 2; o <<= 1) {
#pragma unroll
        for (int q = 0; q < 4; q++) {
            ps[q] += __shfl_xor_sync(0xffffffffu, ps[q], o);
            pd[q] += __shfl_xor_sync(0xffffffffu, pd[q], o);
        }
    }
    if (tig == 0) {
        const int rows[4] = {r0, r1, r2, r3};
#pragma unroll
        for (int q = 0; q < 4; q++) {
            if (rows[q] < NN) {
                g_es[rows[q] * HH + w] = ps[q];
                g_ed[rows[q] * HH + w] = pd[q];
            }
        }
    }
}

// ---------------------------------------------------------------------------
// Fused softmax-aggregate + normalize + head-mean + bias + gelu.
// Warp per dst node (8/block). Lane t owns channels 8t..8t+7.
// FINAL: fuse fc dot + sigmoid, write d_out; else write fp16 g_feath.
// ---------------------------------------------------------------------------
template <bool FINAL>
__global__ void __launch_bounds__(256) aggregate_kernel(const float* __restrict__ bias,
                                                        const float* __restrict__ fcW,
                                                        const float* __restrict__ fcb,
                                                        float* __restrict__ out) {
    __shared__ int    ss[8][32];
    __shared__ float4 ws[8][32];

    const int wid = threadIdx.x >> 5;
    const int lid = threadIdx.x & 31;
    const int n = blockIdx.x * 8 + wid;   // NN == 6250 * 8
    const int head = lid >> 3;

    const int row0 = g_off[n], row1 = g_off[n + 1];
    const float4 edv = *(const float4*)&g_ed[n * 4];

    float acc[8] = {0.f, 0.f, 0.f, 0.f, 0.f, 0.f, 0.f, 0.f};
    float dsum = 0.f;

    for (int base = row0; base < row1; base += 32) {
        int cnt = min(32, row1 - base);
        if (lid < cnt) {
            int s = __ldg(&g_csr[base + lid]);
            ss[wid][lid] = s * HC;
            float4 esv = __ldg((const float4*)&g_es[s * 4]);
            ws[wid][lid] = make_float4(__expf(lrelu(esv.x + edv.x)),
                                       __expf(lrelu(esv.y + edv.y)),
                                       __expf(lrelu(esv.z + edv.z)),
                                       __expf(lrelu(esv.w + edv.w)));
        }
        __syncwarp();
#pragma unroll 4
        for (int e = 0; e < cnt; e++) {
            float wv = ((const float*)&ws[wid][e])[head];
            uint4 hv = *(const uint4*)&g_hh[ss[wid][e] + 8 * lid];
            float2 f0 = __half22float2(*(const __half2*)&hv.x);
            float2 f1 = __half22float2(*(const __half2*)&hv.y);
            float2 f2 = __half22float2(*(const __half2*)&hv.z);
            float2 f3 = __half22float2(*(const __half2*)&hv.w);
            acc[0] += wv * f0.x; acc[1] += wv * f0.y;
            acc[2] += wv * f1.x; acc[3] += wv * f1.y;
            acc[4] += wv * f2.x; acc[5] += wv * f2.y;
            acc[6] += wv * f3.x; acc[7] += wv * f3.y;
            dsum += wv;
        }
        __syncwarp();
    }

    float inv = 1.f / (dsum + 1e-16f);
#pragma unroll
    for (int i = 0; i < 8; i++) {
        acc[i] *= inv;
        acc[i] += __shfl_xor_sync(0xffffffffu, acc[i], 8);
        acc[i] += __shfl_xor_sync(0xffffffffu, acc[i], 16);
    }
    // lanes 0..7 hold head-sums for channels 8*lid..8*lid+7
    if (lid < 8) {
        float gl[8];
#pragma unroll
        for (int i = 0; i < 8; i++) {
            float s = 0.25f * acc[i] + bias[8 * lid + i];
            float t = tanhf(0.7978845608028654f * (s + 0.044715f * s * s * s));
            gl[i] = 0.5f * s * (1.f + t);
        }
        if (FINAL) {
            float p = 0.f;
#pragma unroll
            for (int i = 0; i < 8; i++) p += gl[i] * fcW[8 * lid + i];
#pragma unroll
            for (int o = 1; o <= 4; o <<= 1)
                p += __shfl_xor_sync(0xffu, p, o);
            if (lid == 0) out[n] = 1.f / (1.f + __expf(-(p + fcb[0])));
        } else {
            __half2 outh[4];
#pragma unroll
            for (int i = 0; i < 8; i += 2)
                outh[i >> 1] = __floats2half2_rn(gl[i], gl[i + 1]);
            *(uint4*)&g_feath[n * CC + 8 * lid] = *(uint4*)outh;
        }
    }
}

// ---------------------------------------------------------------------------

extern "C" void kernel_launch(void* const* d_in, const int* in_sizes, int n_in,
                              void* d_out, int out_size) {
    const float* x    = (const float*)d_in[0];
    const int*   ei   = (const int*)d_in[1];
    const float* W1   = (const float*)d_in[2];
    const float* as1  = (const float*)d_in[3];
    const float* ad1  = (const float*)d_in[4];
    const float* b1   = (const float*)d_in[5];
    const float* W2   = (const float*)d_in[6];
    const float* as2  = (const float*)d_in[7];
    const float* ad2  = (const float*)d_in[8];
    const float* b2   = (const float*)d_in[9];
    const float* W3   = (const float*)d_in[10];
    const float* as3  = (const float*)d_in[11];
    const float* ad3  = (const float*)d_in[12];
    const float* b3   = (const float*)d_in[13];
    const float* fcW  = (const float*)d_in[14];
    const float* fcb  = (const float*)d_in[15];

    __half* feath_ptr = nullptr;
    cudaGetSymbolAddress((void**)&feath_ptr, g_feath);
    int* cnt_ptr = nullptr;
    cudaGetSymbolAddress((void**)&cnt_ptr, g_cnt);

    // Fork: CSR build on side stream, overlapped with layer-1 GEMM.
    cudaStream_t s2;
    cudaStreamCreateWithFlags(&s2, cudaStreamNonBlocking);
    cudaEvent_t evFork, evJoin;
    cudaEventCreateWithFlags(&evFork, cudaEventDisableTiming);
    cudaEventCreateWithFlags(&evJoin, cudaEventDisableTiming);

    cudaEventRecord(evFork, 0);
    cudaStreamWaitEvent(s2, evFork, 0);
    cudaMemsetAsync(cnt_ptr, 0, NN * sizeof(int), s2);
    hist_kernel<<<(E2T + 255) / 256, 256, 0, s2>>>(ei);
    scan_kernel<<<1, 1024, 0, s2>>>();
    scatter_kernel<<<(E2T + 255) / 256, 256, 0, s2>>>(ei);
    cudaEventRecord(evJoin, s2);

    // Layer 1 GEMM (independent of CSR)
    convw_kernel<<<(128 * 256 + 255) / 256, 256>>>(W1, 128 * 256);
    hgemm_kernel<128, true><<<(NN + 31) / 32, 128>>>(x, as1, ad1);

    cudaStreamWaitEvent(0, evJoin, 0);
    aggregate_kernel<false><<<NN / 8, 256>>>(b1, nullptr, nullptr, nullptr);

    convw_kernel<<<(64 * 256 + 255) / 256, 256>>>(W2, 64 * 256);
    hgemm_kernel<64, false><<<(NN + 31) / 32, 128>>>(feath_ptr, as2, ad2);
    aggregate_kernel<false><<<NN / 8, 256>>>(b2, nullptr, nullptr, nullptr);

    convw_kernel<<<(64 * 256 + 255) / 256, 256>>>(W3, 64 * 256);
    hgemm_kernel<64, false><<<(NN + 31) / 32, 128>>>(feath_ptr, as3, ad3);
    aggregate_kernel<true><<<NN / 8, 256>>>(b3, fcW, fcb, (float*)d_out);

    cudaStreamDestroy(s2);
    cudaEventDestroy(evFork);
    cudaEventDestroy(evJoin);
}

// round 10
// speedup vs baseline: 4.0186x; 1.0532x over previous
#include <cuda_runtime.h>
#include <cuda_fp16.h>
#include <cuda_fp8.h>

#define NN 50000
#define EE 800000
#define E2T 850000   // EE + NN self loops
#define HH 4
#define CC 64
#define HC 256       // HH*CC

// Scratch (device globals; no allocation allowed)
__device__ unsigned char g_h8[NN * HC];  // fp8 (e4m3) head features for the edge gather
__device__ __half g_feath[NN * CC];      // fp16 layer output after gelu (next GEMM input)
__device__ __half g_wh1[128 * 256];      // fp16 W per layer
__device__ __half g_wh2[64 * 256];
__device__ __half g_wh3[64 * 256];
__device__ float  g_es[NN * HH];
__device__ float  g_ed[NN * HH];
// CSR (built once; edge list identical across layers)
__device__ int g_cnt[NN];
__device__ int g_off[NN + 1];
__device__ int g_cur[NN];
__device__ int g_csr[E2T];               // src indices grouped by dst

__device__ __forceinline__ float lrelu(float x) { return x >= 0.f ? x : 0.2f * x; }

// ---------------------------------------------------------------------------
// CSR build
// ---------------------------------------------------------------------------
__global__ void hist_kernel(const int* __restrict__ ei) {
    int i = blockIdx.x * blockDim.x + threadIdx.x;
    if (i >= E2T) return;
    int dst = (i < EE) ? ei[EE + i] : (i - EE);
    atomicAdd(&g_cnt[dst], 1);
}

// single-block exclusive scan of g_cnt -> g_off/g_cur, int4-vectorized
__global__ void scan_kernel() {
    __shared__ int wsum[32];
    __shared__ int s_total;
    const int tid = threadIdx.x;
    const int lane = tid & 31, wid = tid >> 5;
    constexpr int N4 = NN / 4;  // 12500
    int carry = 0;
    for (int b4 = 0; b4 < N4; b4 += 1024) {
        int i4 = b4 + tid;
        int4 v = make_int4(0, 0, 0, 0);
        if (i4 < N4) v = ((const int4*)g_cnt)[i4];
        int tsum = v.x + v.y + v.z + v.w;
        int s = tsum;
#pragma unroll
        for (int o = 1; o < 32; o <<= 1) {
            int t = __shfl_up_sync(0xffffffffu, s, o);
            if (lane >= o) s += t;
        }
        if (lane == 31) wsum[wid] = s;
        __syncthreads();
        if (wid == 0) {
            int w = wsum[lane];
#pragma unroll
            for (int o = 1; o < 32; o <<= 1) {
                int t = __shfl_up_sync(0xffffffffu, w, o);
                if (lane >= o) w += t;
            }
            wsum[lane] = w;
            if (lane == 31) s_total = w;
        }
        __syncthreads();
        int excl = s - tsum + (wid ? wsum[wid - 1] : 0) + carry;
        if (i4 < N4) {
            int4 o;
            o.x = excl;
            o.y = o.x + v.x;
            o.z = o.y + v.y;
            o.w = o.z + v.z;
            ((int4*)g_off)[i4] = o;
            ((int4*)g_cur)[i4] = o;
        }
        carry += s_total;
        __syncthreads();
    }
    if (tid == 0) g_off[NN] = carry;
}

__global__ void scatter_kernel(const int* __restrict__ ei) {
    int i = blockIdx.x * blockDim.x + threadIdx.x;
    if (i >= E2T) return;
    int src, dst;
    if (i < EE) { src = ei[i]; dst = ei[EE + i]; }
    else        { src = i - EE; dst = src; }
    int pos = atomicAdd(&g_cur[dst], 1);
    g_csr[pos] = src;
}

// ---------------------------------------------------------------------------
// W fp32 -> fp16 (per-layer buffer)
// ---------------------------------------------------------------------------
__global__ void convw_kernel(const float* __restrict__ W, __half* __restrict__ Wh, int n) {
    int i = blockIdx.x * blockDim.x + threadIdx.x;
    if (i < n) Wh[i] = __float2half(W[i]);
}

// ---------------------------------------------------------------------------
// Tensor-core GEMM + attention epilogue.  M=32 tile (predicated tail).
// C[NN,256] = A[NN,K] @ W[K,256], fp16 in, fp32 accum.
// 128 threads / 4 warps; warp w owns cols [64w,64w+64) == head w, all 32 rows.
// Epilogue: fp8 h store + es/ed from fp32 accums, 4-lane shfl reduce.
// ---------------------------------------------------------------------------
template <bool F32>
__device__ __forceinline__ unsigned ldA(const void* A, int row, int col, int K, bool valid) {
    if (!valid) return 0u;
    if (F32) {
        float2 f = *(const float2*)((const float*)A + row * K + col);
        __half2 h = __floats2half2_rn(f.x, f.y);
        return *(unsigned*)&h;
    } else {
        return *(const unsigned*)((const __half*)A + row * K + col);
    }
}

template <int K, bool A_FP32>
__global__ void __launch_bounds__(128) hgemm_kernel(const void* __restrict__ Ain,
                                                    const __half* __restrict__ Wh,
                                                    const float* __restrict__ a_src,
                                                    const float* __restrict__ a_dst) {
    constexpr int KC = 64;            // k rows staged per chunk
    constexpr int NCH = K / KC;       // 2 (layer 1) or 1 (layers 2-3)
    constexpr int SBS = 264;          // smem stride in halves
    __shared__ __half sB[KC][SBS];

    const int tid = threadIdx.x;
    const int w = tid >> 5, lane = tid & 31;
    const int g = lane >> 2, tig = lane & 3;
    const int base = blockIdx.x * 32;
    const int n0 = w * 64;

    const int r0 = base + g,      r1 = base + g + 8;
    const int r2 = base + g + 16, r3 = base + g + 24;
    const bool v2 = r2 < NN, v3 = r3 < NN;

    float c[2][8][4];
#pragma unroll
    for (int rg = 0; rg < 2; rg++)
#pragma unroll
        for (int j = 0; j < 8; j++)
#pragma unroll
            for (int q = 0; q < 4; q++) c[rg][j][q] = 0.f;

    for (int ch = 0; ch < NCH; ch++) {
        for (int idx = tid; idx < KC * 32; idx += 128) {
            int r = idx >> 5, c16 = idx & 31;
            *(uint4*)&sB[r][c16 * 8] =
                *(const uint4*)&Wh[(ch * KC + r) * 256 + c16 * 8];
        }
        __syncthreads();

#pragma unroll
        for (int kk = 0; kk < KC / 16; kk++) {
            const int kg = ch * KC + kk * 16;
            unsigned a0 = ldA<A_FP32>(Ain, r0, kg + 2 * tig,     K, true);
            unsigned a1 = ldA<A_FP32>(Ain, r1, kg + 2 * tig,     K, true);
            unsigned a2 = ldA<A_FP32>(Ain, r0, kg + 2 * tig + 8, K, true);
            unsigned a3 = ldA<A_FP32>(Ain, r1, kg + 2 * tig + 8, K, true);
            unsigned a4 = ldA<A_FP32>(Ain, r2, kg + 2 * tig,     K, v2);
            unsigned a5 = ldA<A_FP32>(Ain, r3, kg + 2 * tig,     K, v3);
            unsigned a6 = ldA<A_FP32>(Ain, r2, kg + 2 * tig + 8, K, v2);
            unsigned a7 = ldA<A_FP32>(Ain, r3, kg + 2 * tig + 8, K, v3);
#pragma unroll
            for (int jp = 0; jp < 4; jp++) {
                unsigned b0, b1, b2, b3;
                unsigned addr = (unsigned)__cvta_generic_to_shared(
                    &sB[kk * 16 + (lane & 15)][n0 + jp * 16 + (lane >> 4) * 8]);
                asm volatile(
                    "ldmatrix.sync.aligned.m8n8.x4.trans.shared.b16 {%0,%1,%2,%3}, [%4];"
                    : "=r"(b0), "=r"(b1), "=r"(b2), "=r"(b3) : "r"(addr));
                asm volatile(
                    "mma.sync.aligned.m16n8k16.row.col.f32.f16.f16.f32 "
                    "{%0,%1,%2,%3}, {%4,%5,%6,%7}, {%8,%9}, {%0,%1,%2,%3};"
                    : "+f"(c[0][2*jp][0]), "+f"(c[0][2*jp][1]), "+f"(c[0][2*jp][2]), "+f"(c[0][2*jp][3])
                    : "r"(a0), "r"(a1), "r"(a2), "r"(a3), "r"(b0), "r"(b1));
                asm volatile(
                    "mma.sync.aligned.m16n8k16.row.col.f32.f16.f16.f32 "
                    "{%0,%1,%2,%3}, {%4,%5,%6,%7}, {%8,%9}, {%0,%1,%2,%3};"
                    : "+f"(c[0][2*jp+1][0]), "+f"(c[0][2*jp+1][1]), "+f"(c[0][2*jp+1][2]), "+f"(c[0][2*jp+1][3])
                    : "r"(a0), "r"(a1), "r"(a2), "r"(a3), "r"(b2), "r"(b3));
                asm volatile(
                    "mma.sync.aligned.m16n8k16.row.col.f32.f16.f16.f32 "
                    "{%0,%1,%2,%3}, {%4,%5,%6,%7}, {%8,%9}, {%0,%1,%2,%3};"
                    : "+f"(c[1][2*jp][0]), "+f"(c[1][2*jp][1]), "+f"(c[1][2*jp][2]), "+f"(c[1][2*jp][3])
                    : "r"(a4), "r"(a5), "r"(a6), "r"(a7), "r"(b0), "r"(b1));
                asm volatile(
                    "mma.sync.aligned.m16n8k16.row.col.f32.f16.f16.f32 "
                    "{%0,%1,%2,%3}, {%4,%5,%6,%7}, {%8,%9}, {%0,%1,%2,%3};"
                    : "+f"(c[1][2*jp+1][0]), "+f"(c[1][2*jp+1][1]), "+f"(c[1][2*jp+1][2]), "+f"(c[1][2*jp+1][3])
                    : "r"(a4), "r"(a5), "r"(a6), "r"(a7), "r"(b2), "r"(b3));
            }
        }
        __syncthreads();
    }

    // Epilogue: fp8 h store + es/ed partials
    float ps[4] = {0.f, 0.f, 0.f, 0.f};
    float pd[4] = {0.f, 0.f, 0.f, 0.f};
#pragma unroll
    for (int j = 0; j < 8; j++) {
        int col = n0 + 8 * j + 2 * tig;
        float2 as2 = *(const float2*)&a_src[col];
        float2 ad2 = *(const float2*)&a_dst[col];
#pragma unroll
        for (int rg = 0; rg < 2; rg++) {
            int rowA = base + 16 * rg + g, rowB = rowA + 8;
            __nv_fp8x2_storage_t p0 = __nv_cvt_float2_to_fp8x2(
                make_float2(c[rg][j][0], c[rg][j][1]), __NV_SATFINITE, __NV_E4M3);
            __nv_fp8x2_storage_t p1 = __nv_cvt_float2_to_fp8x2(
                make_float2(c[rg][j][2], c[rg][j][3]), __NV_SATFINITE, __NV_E4M3);
            if (rowA < NN) *(unsigned short*)&g_h8[rowA * HC + col] = p0;
            if (rowB < NN) *(unsigned short*)&g_h8[rowB * HC + col] = p1;
            ps[2*rg]   += c[rg][j][0] * as2.x + c[rg][j][1] * as2.y;
            pd[2*rg]   += c[rg][j][0] * ad2.x + c[rg][j][1] * ad2.y;
            ps[2*rg+1] += c[rg][j][2] * as2.x + c[rg][j][3] * as2.y;
            pd[2*rg+1] += c[rg][j][2] * ad2.x + c[rg][j][3] * ad2.y;
        }
    }
#pragma unroll
    for (int o = 1; o <= 2; o <<= 1) {
#pragma unroll
        for (int q = 0; q < 4; q++) {
            ps[q] += __shfl_xor_sync(0xffffffffu, ps[q], o);
            pd[q] += __shfl_xor_sync(0xffffffffu, pd[q], o);
        }
    }
    if (tig == 0) {
        const int rows[4] = {r0, r1, r2, r3};
#pragma unroll
        for (int q = 0; q < 4; q++) {
            if (rows[q] < NN) {
                g_es[rows[q] * HH + w] = ps[q];
                g_ed[rows[q] * HH + w] = pd[q];
            }
        }
    }
}

// ---------------------------------------------------------------------------
// Fused softmax-aggregate + normalize + head-mean + bias + gelu.
// Warp per dst node (8/block). Lane t owns channels 8t..8t+7, gathered as
// one 8-byte fp8 load per edge. FINAL: fuse fc dot + sigmoid -> d_out.
// ---------------------------------------------------------------------------
template <bool FINAL>
__global__ void __launch_bounds__(256) aggregate_kernel(const float* __restrict__ bias,
                                                        const float* __restrict__ fcW,
                                                        const float* __restrict__ fcb,
                                                        float* __restrict__ out) {
    __shared__ int    ss[8][32];
    __shared__ float4 ws[8][32];

    const int wid = threadIdx.x >> 5;
    const int lid = threadIdx.x & 31;
    const int n = blockIdx.x * 8 + wid;   // NN == 6250 * 8
    const int head = lid >> 3;

    const int row0 = g_off[n], row1 = g_off[n + 1];
    const float4 edv = *(const float4*)&g_ed[n * 4];

    float acc[8] = {0.f, 0.f, 0.f, 0.f, 0.f, 0.f, 0.f, 0.f};
    float dsum = 0.f;

    for (int base = row0; base < row1; base += 32) {
        int cnt = min(32, row1 - base);
        if (lid < cnt) {
            int s = __ldg(&g_csr[base + lid]);
            ss[wid][lid] = s * HC;
            float4 esv = __ldg((const float4*)&g_es[s * 4]);
            ws[wid][lid] = make_float4(__expf(lrelu(esv.x + edv.x)),
                                       __expf(lrelu(esv.y + edv.y)),
                                       __expf(lrelu(esv.z + edv.z)),
                                       __expf(lrelu(esv.w + edv.w)));
        }
        __syncwarp();
#pragma unroll 4
        for (int e = 0; e < cnt; e++) {
            float wv = ((const float*)&ws[wid][e])[head];
            uint2 hv = *(const uint2*)&g_h8[ss[wid][e] + 8 * lid];
            __half2_raw r0 = __nv_cvt_fp8x2_to_halfraw2((__nv_fp8x2_storage_t)(hv.x),
                                                        __NV_E4M3);
            __half2_raw r1 = __nv_cvt_fp8x2_to_halfraw2((__nv_fp8x2_storage_t)(hv.x >> 16),
                                                        __NV_E4M3);
            __half2_raw r2 = __nv_cvt_fp8x2_to_halfraw2((__nv_fp8x2_storage_t)(hv.y),
                                                        __NV_E4M3);
            __half2_raw r3 = __nv_cvt_fp8x2_to_halfraw2((__nv_fp8x2_storage_t)(hv.y >> 16),
                                                        __NV_E4M3);
            float2 f0 = __half22float2(*(__half2*)&r0);
            float2 f1 = __half22float2(*(__half2*)&r1);
            float2 f2 = __half22float2(*(__half2*)&r2);
            float2 f3 = __half22float2(*(__half2*)&r3);
            acc[0] += wv * f0.x; acc[1] += wv * f0.y;
            acc[2] += wv * f1.x; acc[3] += wv * f1.y;
            acc[4] += wv * f2.x; acc[5] += wv * f2.y;
            acc[6] += wv * f3.x; acc[7] += wv * f3.y;
            dsum += wv;
        }
        __syncwarp();
    }

    float inv = 1.f / (dsum + 1e-16f);
#pragma unroll
    for (int i = 0; i < 8; i++) {
        acc[i] *= inv;
        acc[i] += __shfl_xor_sync(0xffffffffu, acc[i], 8);
        acc[i] += __shfl_xor_sync(0xffffffffu, acc[i], 16);
    }
    // lanes 0..7 hold head-sums for channels 8*lid..8*lid+7
    if (lid < 8) {
        float gl[8];
#pragma unroll
        for (int i = 0; i < 8; i++) {
            float s = 0.25f * acc[i] + bias[8 * lid + i];
            float t = tanhf(0.7978845608028654f * (s + 0.044715f * s * s * s));
            gl[i] = 0.5f * s * (1.f + t);
        }
        if (FINAL) {
            float p = 0.f;
#pragma unroll
            for (int i = 0; i < 8; i++) p += gl[i] * fcW[8 * lid + i];
#pragma unroll
            for (int o = 1; o <= 4; o <<= 1)
                p += __shfl_xor_sync(0xffu, p, o);
            if (lid == 0) out[n] = 1.f / (1.f + __expf(-(p + fcb[0])));
        } else {
            __half2 outh[4];
#pragma unroll
            for (int i = 0; i < 8; i += 2)
                outh[i >> 1] = __floats2half2_rn(gl[i], gl[i + 1]);
            *(uint4*)&g_feath[n * CC + 8 * lid] = *(uint4*)outh;
        }
    }
}

// ---------------------------------------------------------------------------

extern "C" void kernel_launch(void* const* d_in, const int* in_sizes, int n_in,
                              void* d_out, int out_size) {
    const float* x    = (const float*)d_in[0];
    const int*   ei   = (const int*)d_in[1];
    const float* W1   = (const float*)d_in[2];
    const float* as1  = (const float*)d_in[3];
    const float* ad1  = (const float*)d_in[4];
    const float* b1   = (const float*)d_in[5];
    const float* W2   = (const float*)d_in[6];
    const float* as2  = (const float*)d_in[7];
    const float* ad2  = (const float*)d_in[8];
    const float* b2   = (const float*)d_in[9];
    const float* W3   = (const float*)d_in[10];
    const float* as3  = (const float*)d_in[11];
    const float* ad3  = (const float*)d_in[12];
    const float* b3   = (const float*)d_in[13];
    const float* fcW  = (const float*)d_in[14];
    const float* fcb  = (const float*)d_in[15];

    __half *feath_ptr = nullptr, *wh1 = nullptr, *wh2 = nullptr, *wh3 = nullptr;
    int* cnt_ptr = nullptr;
    cudaGetSymbolAddress((void**)&feath_ptr, g_feath);
    cudaGetSymbolAddress((void**)&wh1, g_wh1);
    cudaGetSymbolAddress((void**)&wh2, g_wh2);
    cudaGetSymbolAddress((void**)&wh3, g_wh3);
    cudaGetSymbolAddress((void**)&cnt_ptr, g_cnt);

    // Fork: CSR build + W2/W3 conversion on side stream, overlapped with layer 1.
    cudaStream_t s2;
    cudaStreamCreateWithFlags(&s2, cudaStreamNonBlocking);
    cudaEvent_t evFork, evJoin;
    cudaEventCreateWithFlags(&evFork, cudaEventDisableTiming);
    cudaEventCreateWithFlags(&evJoin, cudaEventDisableTiming);

    cudaEventRecord(evFork, 0);
    cudaStreamWaitEvent(s2, evFork, 0);
    convw_kernel<<<(64 * 256 + 255) / 256, 256, 0, s2>>>(W2, wh2, 64 * 256);
    convw_kernel<<<(64 * 256 + 255) / 256, 256, 0, s2>>>(W3, wh3, 64 * 256);
    cudaMemsetAsync(cnt_ptr, 0, NN * sizeof(int), s2);
    hist_kernel<<<(E2T + 255) / 256, 256, 0, s2>>>(ei);
    scan_kernel<<<1, 1024, 0, s2>>>();
    scatter_kernel<<<(E2T + 255) / 256, 256, 0, s2>>>(ei);
    cudaEventRecord(evJoin, s2);

    // Layer 1 GEMM (independent of CSR)
    convw_kernel<<<(128 * 256 + 255) / 256, 256>>>(W1, wh1, 128 * 256);
    hgemm_kernel<128, true><<<(NN + 31) / 32, 128>>>(x, wh1, as1, ad1);

    cudaStreamWaitEvent(0, evJoin, 0);
    aggregate_kernel<false><<<NN / 8, 256>>>(b1, nullptr, nullptr, nullptr);

    hgemm_kernel<64, false><<<(NN + 31) / 32, 128>>>(feath_ptr, wh2, as2, ad2);
    aggregate_kernel<false><<<NN / 8, 256>>>(b2, nullptr, nullptr, nullptr);

    hgemm_kernel<64, false><<<(NN + 31) / 32, 128>>>(feath_ptr, wh3, as3, ad3);
    aggregate_kernel<true><<<NN / 8, 256>>>(b3, fcW, fcb, (float*)d_out);

    cudaStreamDestroy(s2);
    cudaEventDestroy(evFork);
    cudaEventDestroy(evJoin);
}

// round 11
// speedup vs baseline: 4.3711x; 1.0877x over previous
#include <cuda_runtime.h>
#include <cuda_fp16.h>
#include <cuda_fp8.h>

#define NN 50000
#define EE 800000
#define E2T 850000   // EE + NN self loops
#define HH 4
#define CC 64
#define HC 256       // HH*CC

// Scratch (device globals; no allocation allowed)
__device__ unsigned char g_h8[NN * HC];  // fp8 (e4m3) head features for the edge gather
__device__ __half g_feath[NN * CC];      // fp16 layer output after gelu (next GEMM input)
__device__ __half g_wh1[128 * 256];      // fp16 W per layer
__device__ __half g_wh2[64 * 256];
__device__ __half g_wh3[64 * 256];
__device__ float  g_es[NN * HH];
__device__ float  g_ed[NN * HH];
// CSR (built once; edge list identical across layers)
__device__ int g_cnt[NN];
__device__ int g_off[NN + 1];
__device__ int g_cur[NN];
__device__ int g_csr[E2T];               // src indices grouped by dst
__device__ int g_bsum[16];               // per-scan1-block sums

__device__ __forceinline__ float lrelu(float x) { return x >= 0.f ? x : 0.2f * x; }

// ---------------------------------------------------------------------------
// CSR build
// ---------------------------------------------------------------------------
__global__ void hist_kernel(const int* __restrict__ ei) {
    int i = blockIdx.x * blockDim.x + threadIdx.x;
    if (i >= E2T) return;
    int dst = (i < EE) ? ei[EE + i] : (i - EE);
    atomicAdd(&g_cnt[dst], 1);
}

// Multi-block exclusive scan: scan1 (block-local) -> scan2 (block sums) -> scan3 (add).
__global__ void scan1_kernel() {   // 13 blocks x 1024 threads, int4 per thread
    __shared__ int wsum[32];
    const int tid = threadIdx.x;
    const int lane = tid & 31, wid = tid >> 5;
    constexpr int N4 = NN / 4;  // 12500
    int i4 = blockIdx.x * 1024 + tid;
    int4 v = make_int4(0, 0, 0, 0);
    if (i4 < N4) v = ((const int4*)g_cnt)[i4];
    int tsum = v.x + v.y + v.z + v.w;
    int s = tsum;
#pragma unroll
    for (int o = 1; o < 32; o <<= 1) {
        int t = __shfl_up_sync(0xffffffffu, s, o);
        if (lane >= o) s += t;
    }
    if (lane == 31) wsum[wid] = s;
    __syncthreads();
    if (wid == 0) {
        int w = wsum[lane];
#pragma unroll
        for (int o = 1; o < 32; o <<= 1) {
            int t = __shfl_up_sync(0xffffffffu, w, o);
            if (lane >= o) w += t;
        }
        wsum[lane] = w;
        if (lane == 31) g_bsum[blockIdx.x] = w;   // block total
    }
    __syncthreads();
    int excl = s - tsum + (wid ? wsum[wid - 1] : 0);
    if (i4 < N4) {
        int4 o;
        o.x = excl;
        o.y = o.x + v.x;
        o.z = o.y + v.y;
        o.w = o.z + v.z;
        ((int4*)g_off)[i4] = o;
    }
}

__global__ void scan2_kernel() {   // 1 warp: exclusive scan of 13 block sums
    int lane = threadIdx.x;
    int v = (lane < 13) ? g_bsum[lane] : 0;
    int s = v;
#pragma unroll
    for (int o = 1; o < 32; o <<= 1) {
        int t = __shfl_up_sync(0xffffffffu, s, o);
        if (lane >= o) s += t;
    }
    if (lane < 13) g_bsum[lane] = s - v;
}

__global__ void scan3_kernel() {   // add block offsets, fill g_cur
    constexpr int N4 = NN / 4;
    int i4 = blockIdx.x * 1024 + threadIdx.x;
    if (i4 < N4) {
        int add = g_bsum[i4 >> 10];
        int4 o = ((const int4*)g_off)[i4];
        o.x += add; o.y += add; o.z += add; o.w += add;
        ((int4*)g_off)[i4] = o;
        ((int4*)g_cur)[i4] = o;
    }
    if (i4 == 0) g_off[NN] = E2T;
}

__global__ void scatter_kernel(const int* __restrict__ ei) {
    int i = blockIdx.x * blockDim.x + threadIdx.x;
    if (i >= E2T) return;
    int src, dst;
    if (i < EE) { src = ei[i]; dst = ei[EE + i]; }
    else        { src = i - EE; dst = src; }
    int pos = atomicAdd(&g_cur[dst], 1);
    g_csr[pos] = src;
}

// ---------------------------------------------------------------------------
// W fp32 -> fp16 (per-layer buffer)
// ---------------------------------------------------------------------------
__global__ void convw_kernel(const float* __restrict__ W, __half* __restrict__ Wh, int n) {
    int i = blockIdx.x * blockDim.x + threadIdx.x;
    if (i < n) Wh[i] = __float2half(W[i]);
}

// ---------------------------------------------------------------------------
// Tensor-core GEMM + attention epilogue.  M=64 tile, 256 threads / 8 warps.
// Warp w: head = w&3 (cols [64*head, 64*head+64)), row-half = w>>2 (32 rows).
// C[NN,256] = A[NN,K] @ W[K,256], fp16 in, fp32 accum; predicated tail.
// Epilogue: fp8 h store + es/ed from fp32 accums, 4-lane shfl reduce.
// ---------------------------------------------------------------------------
template <bool F32>
__device__ __forceinline__ unsigned ldA(const void* A, int row, int col, int K, bool valid) {
    if (!valid) return 0u;
    if (F32) {
        float2 f = *(const float2*)((const float*)A + row * K + col);
        __half2 h = __floats2half2_rn(f.x, f.y);
        return *(unsigned*)&h;
    } else {
        return *(const unsigned*)((const __half*)A + row * K + col);
    }
}

template <int K, bool A_FP32>
__global__ void __launch_bounds__(256) hgemm_kernel(const void* __restrict__ Ain,
                                                    const __half* __restrict__ Wh,
                                                    const float* __restrict__ a_src,
                                                    const float* __restrict__ a_dst) {
    constexpr int KC = 64;            // k rows staged per chunk
    constexpr int NCH = K / KC;       // 2 (layer 1) or 1 (layers 2-3)
    constexpr int SBS = 264;          // smem stride in halves
    __shared__ __half sB[KC][SBS];

    const int tid = threadIdx.x;
    const int wfull = tid >> 5, lane = tid & 31;
    const int head = wfull & 3, rh = wfull >> 2;
    const int g = lane >> 2, tig = lane & 3;
    const int base = blockIdx.x * 64 + rh * 32;
    const int n0 = head * 64;

    const int r0 = base + g,      r1 = base + g + 8;
    const int r2 = base + g + 16, r3 = base + g + 24;
    const bool v0 = r0 < NN, v1 = r1 < NN, v2 = r2 < NN, v3 = r3 < NN;

    float c[2][8][4];
#pragma unroll
    for (int rg = 0; rg < 2; rg++)
#pragma unroll
        for (int j = 0; j < 8; j++)
#pragma unroll
            for (int q = 0; q < 4; q++) c[rg][j][q] = 0.f;

    for (int ch = 0; ch < NCH; ch++) {
        for (int idx = tid; idx < KC * 32; idx += 256) {
            int r = idx >> 5, c16 = idx & 31;
            *(uint4*)&sB[r][c16 * 8] =
                *(const uint4*)&Wh[(ch * KC + r) * 256 + c16 * 8];
        }
        __syncthreads();

#pragma unroll
        for (int kk = 0; kk < KC / 16; kk++) {
            const int kg = ch * KC + kk * 16;
            unsigned a0 = ldA<A_FP32>(Ain, r0, kg + 2 * tig,     K, v0);
            unsigned a1 = ldA<A_FP32>(Ain, r1, kg + 2 * tig,     K, v1);
            unsigned a2 = ldA<A_FP32>(Ain, r0, kg + 2 * tig + 8, K, v0);
            unsigned a3 = ldA<A_FP32>(Ain, r1, kg + 2 * tig + 8, K, v1);
            unsigned a4 = ldA<A_FP32>(Ain, r2, kg + 2 * tig,     K, v2);
            unsigned a5 = ldA<A_FP32>(Ain, r3, kg + 2 * tig,     K, v3);
            unsigned a6 = ldA<A_FP32>(Ain, r2, kg + 2 * tig + 8, K, v2);
            unsigned a7 = ldA<A_FP32>(Ain, r3, kg + 2 * tig + 8, K, v3);
#pragma unroll
            for (int jp = 0; jp < 4; jp++) {
                unsigned b0, b1, b2, b3;
                unsigned addr = (unsigned)__cvta_generic_to_shared(
                    &sB[kk * 16 + (lane & 15)][n0 + jp * 16 + (lane >> 4) * 8]);
                asm volatile(
                    "ldmatrix.sync.aligned.m8n8.x4.trans.shared.b16 {%0,%1,%2,%3}, [%4];"
                    : "=r"(b0), "=r"(b1), "=r"(b2), "=r"(b3) : "r"(addr));
                asm volatile(
                    "mma.sync.aligned.m16n8k16.row.col.f32.f16.f16.f32 "
                    "{%0,%1,%2,%3}, {%4,%5,%6,%7}, {%8,%9}, {%0,%1,%2,%3};"
                    : "+f"(c[0][2*jp][0]), "+f"(c[0][2*jp][1]), "+f"(c[0][2*jp][2]), "+f"(c[0][2*jp][3])
                    : "r"(a0), "r"(a1), "r"(a2), "r"(a3), "r"(b0), "r"(b1));
                asm volatile(
                    "mma.sync.aligned.m16n8k16.row.col.f32.f16.f16.f32 "
                    "{%0,%1,%2,%3}, {%4,%5,%6,%7}, {%8,%9}, {%0,%1,%2,%3};"
                    : "+f"(c[0][2*jp+1][0]), "+f"(c[0][2*jp+1][1]), "+f"(c[0][2*jp+1][2]), "+f"(c[0][2*jp+1][3])
                    : "r"(a0), "r"(a1), "r"(a2), "r"(a3), "r"(b2), "r"(b3));
                asm volatile(
                    "mma.sync.aligned.m16n8k16.row.col.f32.f16.f16.f32 "
                    "{%0,%1,%2,%3}, {%4,%5,%6,%7}, {%8,%9}, {%0,%1,%2,%3};"
                    : "+f"(c[1][2*jp][0]), "+f"(c[1][2*jp][1]), "+f"(c[1][2*jp][2]), "+f"(c[1][2*jp][3])
                    : "r"(a4), "r"(a5), "r"(a6), "r"(a7), "r"(b0), "r"(b1));
                asm volatile(
                    "mma.sync.aligned.m16n8k16.row.col.f32.f16.f16.f32 "
                    "{%0,%1,%2,%3}, {%4,%5,%6,%7}, {%8,%9}, {%0,%1,%2,%3};"
                    : "+f"(c[1][2*jp+1][0]), "+f"(c[1][2*jp+1][1]), "+f"(c[1][2*jp+1][2]), "+f"(c[1][2*jp+1][3])
                    : "r"(a4), "r"(a5), "r"(a6), "r"(a7), "r"(b2), "r"(b3));
            }
        }
        __syncthreads();
    }

    // Epilogue: fp8 h store + es/ed partials
    float ps[4] = {0.f, 0.f, 0.f, 0.f};
    float pd[4] = {0.f, 0.f, 0.f, 0.f};
#pragma unroll
    for (int j = 0; j < 8; j++) {
        int col = n0 + 8 * j + 2 * tig;
        float2 as2 = *(const float2*)&a_src[col];
        float2 ad2 = *(const float2*)&a_dst[col];
#pragma unroll
        for (int rg = 0; rg < 2; rg++) {
            int rowA = base + 16 * rg + g, rowB = rowA + 8;
            __nv_fp8x2_storage_t p0 = __nv_cvt_float2_to_fp8x2(
                make_float2(c[rg][j][0], c[rg][j][1]), __NV_SATFINITE, __NV_E4M3);
            __nv_fp8x2_storage_t p1 = __nv_cvt_float2_to_fp8x2(
                make_float2(c[rg][j][2], c[rg][j][3]), __NV_SATFINITE, __NV_E4M3);
            if (rowA < NN) *(unsigned short*)&g_h8[rowA * HC + col] = p0;
            if (rowB < NN) *(unsigned short*)&g_h8[rowB * HC + col] = p1;
            ps[2*rg]   += c[rg][j][0] * as2.x + c[rg][j][1] * as2.y;
            pd[2*rg]   += c[rg][j][0] * ad2.x + c[rg][j][1] * ad2.y;
            ps[2*rg+1] += c[rg][j][2] * as2.x + c[rg][j][3] * as2.y;
            pd[2*rg+1] += c[rg][j][2] * ad2.x + c[rg][j][3] * ad2.y;
        }
    }
#pragma unroll
    for (int o = 1; o <= 2; o <<= 1) {
#pragma unroll
        for (int q = 0; q < 4; q++) {
            ps[q] += __shfl_xor_sync(0xffffffffu, ps[q], o);
            pd[q] += __shfl_xor_sync(0xffffffffu, pd[q], o);
        }
    }
    if (tig == 0) {
        const int rows[4] = {r0, r1, r2, r3};
#pragma unroll
        for (int q = 0; q < 4; q++) {
            if (rows[q] < NN) {
                g_es[rows[q] * HH + head] = ps[q];
                g_ed[rows[q] * HH + head] = pd[q];
            }
        }
    }
}

// ---------------------------------------------------------------------------
// Fused softmax-aggregate + normalize + head-mean + bias + gelu.
// Warp per dst node (8/block). Lane t owns channels 8t..8t+7, gathered as
// one 8-byte fp8 load per edge. FINAL: fuse fc dot + sigmoid -> d_out.
// ---------------------------------------------------------------------------
template <bool FINAL>
__global__ void __launch_bounds__(256) aggregate_kernel(const float* __restrict__ bias,
                                                        const float* __restrict__ fcW,
                                                        const float* __restrict__ fcb,
                                                        float* __restrict__ out) {
    __shared__ int    ss[8][32];
    __shared__ float4 ws[8][32];

    const int wid = threadIdx.x >> 5;
    const int lid = threadIdx.x & 31;
    const int n = blockIdx.x * 8 + wid;   // NN == 6250 * 8
    const int head = lid >> 3;

    const int row0 = g_off[n], row1 = g_off[n + 1];
    const float4 edv = *(const float4*)&g_ed[n * 4];

    float acc[8] = {0.f, 0.f, 0.f, 0.f, 0.f, 0.f, 0.f, 0.f};
    float dsum = 0.f;

    for (int base = row0; base < row1; base += 32) {
        int cnt = min(32, row1 - base);
        if (lid < cnt) {
            int s = __ldg(&g_csr[base + lid]);
            ss[wid][lid] = s * HC;
            float4 esv = __ldg((const float4*)&g_es[s * 4]);
            ws[wid][lid] = make_float4(__expf(lrelu(esv.x + edv.x)),
                                       __expf(lrelu(esv.y + edv.y)),
                                       __expf(lrelu(esv.z + edv.z)),
                                       __expf(lrelu(esv.w + edv.w)));
        }
        __syncwarp();
#pragma unroll 4
        for (int e = 0; e < cnt; e++) {
            float wv = ((const float*)&ws[wid][e])[head];
            uint2 hv = *(const uint2*)&g_h8[ss[wid][e] + 8 * lid];
            __half2_raw r0 = __nv_cvt_fp8x2_to_halfraw2((__nv_fp8x2_storage_t)(hv.x),
                                                        __NV_E4M3);
            __half2_raw r1 = __nv_cvt_fp8x2_to_halfraw2((__nv_fp8x2_storage_t)(hv.x >> 16),
                                                        __NV_E4M3);
            __half2_raw r2 = __nv_cvt_fp8x2_to_halfraw2((__nv_fp8x2_storage_t)(hv.y),
                                                        __NV_E4M3);
            __half2_raw r3 = __nv_cvt_fp8x2_to_halfraw2((__nv_fp8x2_storage_t)(hv.y >> 16),
                                                        __NV_E4M3);
            float2 f0 = __half22float2(*(__half2*)&r0);
            float2 f1 = __half22float2(*(__half2*)&r1);
            float2 f2 = __half22float2(*(__half2*)&r2);
            float2 f3 = __half22float2(*(__half2*)&r3);
            acc[0] += wv * f0.x; acc[1] += wv * f0.y;
            acc[2] += wv * f1.x; acc[3] += wv * f1.y;
            acc[4] += wv * f2.x; acc[5] += wv * f2.y;
            acc[6] += wv * f3.x; acc[7] += wv * f3.y;
            dsum += wv;
        }
        __syncwarp();
    }

    float inv = 1.f / (dsum + 1e-16f);
#pragma unroll
    for (int i = 0; i < 8; i++) {
        acc[i] *= inv;
        acc[i] += __shfl_xor_sync(0xffffffffu, acc[i], 8);
        acc[i] += __shfl_xor_sync(0xffffffffu, acc[i], 16);
    }
    // lanes 0..7 hold head-sums for channels 8*lid..8*lid+7
    if (lid < 8) {
        float gl[8];
#pragma unroll
        for (int i = 0; i < 8; i++) {
            float s = 0.25f * acc[i] + bias[8 * lid + i];
            float t = tanhf(0.7978845608028654f * (s + 0.044715f * s * s * s));
            gl[i] = 0.5f * s * (1.f + t);
        }
        if (FINAL) {
            float p = 0.f;
#pragma unroll
            for (int i = 0; i < 8; i++) p += gl[i] * fcW[8 * lid + i];
#pragma unroll
            for (int o = 1; o <= 4; o <<= 1)
                p += __shfl_xor_sync(0xffu, p, o);
            if (lid == 0) out[n] = 1.f / (1.f + __expf(-(p + fcb[0])));
        } else {
            __half2 outh[4];
#pragma unroll
            for (int i = 0; i < 8; i += 2)
                outh[i >> 1] = __floats2half2_rn(gl[i], gl[i + 1]);
            *(uint4*)&g_feath[n * CC + 8 * lid] = *(uint4*)outh;
        }
    }
}

// ---------------------------------------------------------------------------

extern "C" void kernel_launch(void* const* d_in, const int* in_sizes, int n_in,
                              void* d_out, int out_size) {
    const float* x    = (const float*)d_in[0];
    const int*   ei   = (const int*)d_in[1];
    const float* W1   = (const float*)d_in[2];
    const float* as1  = (const float*)d_in[3];
    const float* ad1  = (const float*)d_in[4];
    const float* b1   = (const float*)d_in[5];
    const float* W2   = (const float*)d_in[6];
    const float* as2  = (const float*)d_in[7];
    const float* ad2  = (const float*)d_in[8];
    const float* b2   = (const float*)d_in[9];
    const float* W3   = (const float*)d_in[10];
    const float* as3  = (const float*)d_in[11];
    const float* ad3  = (const float*)d_in[12];
    const float* b3   = (const float*)d_in[13];
    const float* fcW  = (const float*)d_in[14];
    const float* fcb  = (const float*)d_in[15];

    __half *feath_ptr = nullptr, *wh1 = nullptr, *wh2 = nullptr, *wh3 = nullptr;
    int* cnt_ptr = nullptr;
    cudaGetSymbolAddress((void**)&feath_ptr, g_feath);
    cudaGetSymbolAddress((void**)&wh1, g_wh1);
    cudaGetSymbolAddress((void**)&wh2, g_wh2);
    cudaGetSymbolAddress((void**)&wh3, g_wh3);
    cudaGetSymbolAddress((void**)&cnt_ptr, g_cnt);

    // Fork: CSR build on side stream, overlapped with layer-1 convw+GEMM.
    cudaStream_t s2;
    cudaStreamCreateWithFlags(&s2, cudaStreamNonBlocking);
    cudaEvent_t evFork, evJoin, evW;
    cudaEventCreateWithFlags(&evFork, cudaEventDisableTiming);
    cudaEventCreateWithFlags(&evJoin, cudaEventDisableTiming);
    cudaEventCreateWithFlags(&evW, cudaEventDisableTiming);

    cudaEventRecord(evFork, 0);
    cudaStreamWaitEvent(s2, evFork, 0);
    cudaMemsetAsync(cnt_ptr, 0, NN * sizeof(int), s2);
    hist_kernel<<<(E2T + 255) / 256, 256, 0, s2>>>(ei);
    scan1_kernel<<<13, 1024, 0, s2>>>();
    scan2_kernel<<<1, 32, 0, s2>>>();
    scan3_kernel<<<13, 1024, 0, s2>>>();
    scatter_kernel<<<(E2T + 255) / 256, 256, 0, s2>>>(ei);
    cudaEventRecord(evJoin, s2);
    // W2/W3 conversion after the join point; gated separately before hgemm2.
    convw_kernel<<<(64 * 256 + 255) / 256, 256, 0, s2>>>(W2, wh2, 64 * 256);
    convw_kernel<<<(64 * 256 + 255) / 256, 256, 0, s2>>>(W3, wh3, 64 * 256);
    cudaEventRecord(evW, s2);

    // Layer 1 (independent of CSR)
    convw_kernel<<<(128 * 256 + 255) / 256, 256>>>(W1, wh1, 128 * 256);
    hgemm_kernel<128, true><<<(NN + 63) / 64, 256>>>(x, wh1, as1, ad1);

    cudaStreamWaitEvent(0, evJoin, 0);
    aggregate_kernel<false><<<NN / 8, 256>>>(b1, nullptr, nullptr, nullptr);

    cudaStreamWaitEvent(0, evW, 0);
    hgemm_kernel<64, false><<<(NN + 63) / 64, 256>>>(feath_ptr, wh2, as2, ad2);
    aggregate_kernel<false><<<NN / 8, 256>>>(b2, nullptr, nullptr, nullptr);

    hgemm_kernel<64, false><<<(NN + 63) / 64, 256>>>(feath_ptr, wh3, as3, ad3);
    aggregate_kernel<true><<<NN / 8, 256>>>(b3, fcW, fcb, (float*)d_out);

    cudaStreamDestroy(s2);
    cudaEventDestroy(evFork);
    cudaEventDestroy(evJoin);
    cudaEventDestroy(evW);
}